// round 2
// baseline (speedup 1.0000x reference)
#include <cuda_runtime.h>
#include <stdint.h>

#define SEQ   2048
#define HID   768
#define NH    12
#define HD    64
#define BATCH 2
#define MROWS 4096   // BATCH*SEQ

// Scratch (device globals: allocation rules forbid cudaMalloc)
__device__ float g_qkv[3u * MROWS * HID];   // q | k | v, each [MROWS][HID]
__device__ float g_mrg[(size_t)MROWS * HID];
__device__ unsigned char g_mask[MROWS];     // normalized 0/1 mask, [B][SEQ]

// ---------------------------------------------------------------------------
// Normalize the attention mask into g_mask regardless of whether the harness
// stored the bool array as uint8 (1 byte/elem) or int32 (4 bytes/elem).
// Detection: interpret first n bytes; if any byte at i%4!=0 is nonzero the
// layout must be uint8 (an int32-encoded 0/1 array has those bytes == 0).
// Deterministic for fixed input -> graph-replay safe.
// ---------------------------------------------------------------------------
__global__ void decode_mask(const unsigned char* __restrict__ m, int n)
{
    __shared__ int nonz;
    if (threadIdx.x == 0) nonz = 0;
    __syncthreads();
    for (int i = threadIdx.x; i < n; i += blockDim.x)
        if ((i & 3) && m[i]) atomicOr(&nonz, 1);
    __syncthreads();
    const bool is_u8 = (nonz != 0);
    const int* mi = (const int*)m;
    for (int i = threadIdx.x; i < n; i += blockDim.x)
        g_mask[i] = is_u8 ? (m[i] != 0) : (mi[i] != 0);
}

// ---------------------------------------------------------------------------
// C = A(M,K) * B(N,K)^T, row-major, M=4096, N=K=768.
// blockIdx.z selects B0/B1/B2 and writes slab z of the destination.
// a_from_mrg: read A from g_mrg. c_to_qkv: write to g_qkv slabs.
// ---------------------------------------------------------------------------
__global__ __launch_bounds__(256, 2)
void sgemm_nt(const float* __restrict__ A_ext, int a_from_mrg,
              const float* __restrict__ B0,
              const float* __restrict__ B1,
              const float* __restrict__ B2,
              float* __restrict__ C_ext, int c_to_qkv)
{
    const int K = HID, N = HID;
    const float* A = a_from_mrg ? (const float*)g_mrg : A_ext;
    const float* B = (blockIdx.z == 0) ? B0 : ((blockIdx.z == 1) ? B1 : B2);
    float* Cb = c_to_qkv ? (g_qkv + (size_t)blockIdx.z * MROWS * HID) : C_ext;

    __shared__ float As[8][128];
    __shared__ float Bs[8][128];

    const int tid = threadIdx.x;
    const int bm = blockIdx.y * 128;
    const int bn = blockIdx.x * 128;
    const int lr = tid >> 1;            // 0..127 load row
    const int lc = (tid & 1) << 2;      // 0 or 4
    const float* Ap = A + (size_t)(bm + lr) * K + lc;
    const float* Bp = B + (size_t)(bn + lr) * K + lc;
    const int tm = (tid >> 4) << 3;     // 0..120
    const int tn = (tid & 15) << 3;     // 0..120

    float acc[8][8];
    #pragma unroll
    for (int i = 0; i < 8; i++)
        #pragma unroll
        for (int j = 0; j < 8; j++) acc[i][j] = 0.f;

    for (int k0 = 0; k0 < K; k0 += 8) {
        float4 a = *(const float4*)(Ap + k0);
        float4 b = *(const float4*)(Bp + k0);
        As[lc + 0][lr] = a.x; As[lc + 1][lr] = a.y;
        As[lc + 2][lr] = a.z; As[lc + 3][lr] = a.w;
        Bs[lc + 0][lr] = b.x; Bs[lc + 1][lr] = b.y;
        Bs[lc + 2][lr] = b.z; Bs[lc + 3][lr] = b.w;
        __syncthreads();
        #pragma unroll
        for (int kk = 0; kk < 8; kk++) {
            float ar[8], br[8];
            *(float4*)&ar[0] = *(const float4*)&As[kk][tm];
            *(float4*)&ar[4] = *(const float4*)&As[kk][tm + 4];
            *(float4*)&br[0] = *(const float4*)&Bs[kk][tn];
            *(float4*)&br[4] = *(const float4*)&Bs[kk][tn + 4];
            #pragma unroll
            for (int i = 0; i < 8; i++)
                #pragma unroll
                for (int j = 0; j < 8; j++)
                    acc[i][j] = fmaf(ar[i], br[j], acc[i][j]);
        }
        __syncthreads();
    }

    #pragma unroll
    for (int i = 0; i < 8; i++) {
        float* Cp = Cb + (size_t)(bm + tm + i) * N + bn + tn;
        *(float4*)(Cp)     = make_float4(acc[i][0], acc[i][1], acc[i][2], acc[i][3]);
        *(float4*)(Cp + 4) = make_float4(acc[i][4], acc[i][5], acc[i][6], acc[i][7]);
    }
}

// ---------------------------------------------------------------------------
// Flash attention: one CTA per (b, h, 64-row q tile). hd=64.
// Q tile plain float4 layout. K/V tiles XOR-chunk-swizzled so d-major (QK)
// and kv-major (PV) LDS.128 reads are both conflict-free. P aliases the K
// tile. Online softmax; mask as additive -1e30 bias.
// ---------------------------------------------------------------------------
__global__ __launch_bounds__(256)
void attn_kernel()
{
    __shared__ float4 Qs4[64 * 16];
    __shared__ float4 KP4[64 * 16];   // K tile, then P tile
    __shared__ float4 Vs4[64 * 16];
    float* KPf = (float*)KP4;

    const int tid = threadIdx.x;
    const int tx = tid & 15;
    const int ty = tid >> 4;
    const int q0 = blockIdx.x * 64;
    const int b  = blockIdx.y / NH;
    const int h  = blockIdx.y % NH;

    const size_t base = (size_t)b * SEQ * HID + h * HD;
    const float* Qg = g_qkv + base;
    const float* Kg = g_qkv + (size_t)MROWS * HID + base;
    const float* Vg = g_qkv + 2ull * MROWS * HID + base;
    const unsigned char* mk = g_mask + b * SEQ;

    const int lrow0  = tid >> 4;   // 0..15
    const int lchunk = tid & 15;   // float4 chunk in row (d/4)

    // Q tile (once per block)
    #pragma unroll
    for (int p = 0; p < 4; p++) {
        int r = p * 16 + lrow0;
        Qs4[r * 16 + lchunk] =
            *(const float4*)(Qg + (size_t)(q0 + r) * HID + lchunk * 4);
    }

    int row[4], scol[4];
    #pragma unroll
    for (int i = 0; i < 4; i++) row[i] = ty * 4 + i;
    #pragma unroll
    for (int j = 0; j < 4; j++) scol[j] = tx + 16 * j;

    float m_i[4], l_i[4], o[4][4];
    #pragma unroll
    for (int i = 0; i < 4; i++) {
        m_i[i] = -1e30f; l_i[i] = 0.f;
        #pragma unroll
        for (int j = 0; j < 4; j++) o[i][j] = 0.f;
    }

    for (int t = 0; t < SEQ / 64; t++) {
        const int kk0 = t * 64;
        __syncthreads();   // prior PV reads done before overwriting KP/Vs
        #pragma unroll
        for (int p = 0; p < 4; p++) {
            int r = p * 16 + lrow0;
            const size_t goff = (size_t)(kk0 + r) * HID + lchunk * 4;
            float4 kt = *(const float4*)(Kg + goff);
            float4 vt = *(const float4*)(Vg + goff);
            int sc = lchunk ^ (r & 15);     // XOR chunk swizzle
            KP4[r * 16 + sc] = kt;
            Vs4[r * 16 + sc] = vt;
        }
        __syncthreads();

        float bias[4];
        #pragma unroll
        for (int j = 0; j < 4; j++)
            bias[j] = mk[kk0 + scol[j]] ? 0.f : -1e30f;

        // S = Q * K^T  (chunked over d)
        float s[4][4];
        #pragma unroll
        for (int i = 0; i < 4; i++)
            #pragma unroll
            for (int j = 0; j < 4; j++) s[i][j] = 0.f;

        #pragma unroll
        for (int cc = 0; cc < 16; cc++) {
            float4 aq[4], bk[4];
            #pragma unroll
            for (int i = 0; i < 4; i++) aq[i] = Qs4[row[i] * 16 + cc];
            #pragma unroll
            for (int j = 0; j < 4; j++) bk[j] = KP4[scol[j] * 16 + (cc ^ tx)];
            #pragma unroll
            for (int i = 0; i < 4; i++)
                #pragma unroll
                for (int j = 0; j < 4; j++) {
                    s[i][j] = fmaf(aq[i].x, bk[j].x, s[i][j]);
                    s[i][j] = fmaf(aq[i].y, bk[j].y, s[i][j]);
                    s[i][j] = fmaf(aq[i].z, bk[j].z, s[i][j]);
                    s[i][j] = fmaf(aq[i].w, bk[j].w, s[i][j]);
                }
        }

        // online softmax (row stats across the 16 tx lanes)
        #pragma unroll
        for (int i = 0; i < 4; i++) {
            float mt = m_i[i];
            #pragma unroll
            for (int j = 0; j < 4; j++) {
                s[i][j] = fmaf(s[i][j], 0.125f, bias[j]);
                mt = fmaxf(mt, s[i][j]);
            }
            #pragma unroll
            for (int w = 1; w < 16; w <<= 1)
                mt = fmaxf(mt, __shfl_xor_sync(0xffffffffu, mt, w));
            float alpha = __expf(m_i[i] - mt);
            float rs = 0.f;
            #pragma unroll
            for (int j = 0; j < 4; j++) {
                s[i][j] = __expf(s[i][j] - mt);
                rs += s[i][j];
            }
            #pragma unroll
            for (int w = 1; w < 16; w <<= 1)
                rs += __shfl_xor_sync(0xffffffffu, rs, w);
            l_i[i] = l_i[i] * alpha + rs;
            m_i[i] = mt;
            #pragma unroll
            for (int j = 0; j < 4; j++) o[i][j] *= alpha;
        }

        __syncthreads();   // all K reads done before P overwrites KP
        #pragma unroll
        for (int i = 0; i < 4; i++)
            #pragma unroll
            for (int j = 0; j < 4; j++)
                KPf[row[i] * 64 + scol[j]] = s[i][j];
        __syncthreads();

        // O += P * V   (output cols of this thread: 4*tx .. 4*tx+3)
        #pragma unroll
        for (int c4 = 0; c4 < 16; c4++) {
            float4 pr[4];
            #pragma unroll
            for (int i = 0; i < 4; i++)
                pr[i] = ((const float4*)KPf)[row[i] * 16 + c4];
            #pragma unroll
            for (int u = 0; u < 4; u++) {
                int kv = c4 * 4 + u;
                float4 vv = Vs4[kv * 16 + (tx ^ (kv & 15))];
                #pragma unroll
                for (int i = 0; i < 4; i++) {
                    float p = ((const float*)&pr[i])[u];
                    o[i][0] = fmaf(p, vv.x, o[i][0]);
                    o[i][1] = fmaf(p, vv.y, o[i][1]);
                    o[i][2] = fmaf(p, vv.z, o[i][2]);
                    o[i][3] = fmaf(p, vv.w, o[i][3]);
                }
            }
        }
    }

    // epilogue: normalize, write merged [b, s, h*64 + d]
    #pragma unroll
    for (int i = 0; i < 4; i++) {
        float inv = 1.f / l_i[i];
        float4 r4 = make_float4(o[i][0] * inv, o[i][1] * inv,
                                o[i][2] * inv, o[i][3] * inv);
        *(float4*)(g_mrg + (size_t)(b * SEQ + q0 + row[i]) * HID + h * HD + tx * 4) = r4;
    }
}

// ---------------------------------------------------------------------------
extern "C" void kernel_launch(void* const* d_in, const int* in_sizes, int n_in,
                              void* d_out, int out_size)
{
    const float*         x    = (const float*)d_in[0];
    const unsigned char* mask = (const unsigned char*)d_in[1];
    const float*         Wq   = (const float*)d_in[2];
    const float*         Wk   = (const float*)d_in[3];
    const float*         Wv   = (const float*)d_in[4];
    const float*         Wp   = (const float*)d_in[5];
    float*               out  = (float*)d_out;

    dim3 blk(256);
    // Mask normalization (handles uint8 or int32 bool serialization)
    decode_mask<<<1, 256>>>(mask, in_sizes[1]);
    // QKV projections (fused into one launch via gridDim.z)
    sgemm_nt<<<dim3(HID / 128, MROWS / 128, 3), blk>>>(x, 0, Wq, Wk, Wv, nullptr, 1);
    // Attention
    attn_kernel<<<dim3(SEQ / 64, BATCH * NH), blk>>>();
    // Output projection
    sgemm_nt<<<dim3(HID / 128, MROWS / 128, 1), blk>>>(nullptr, 1, Wp, Wp, Wp, out, 0);
}

// round 8
// speedup vs baseline: 1.3210x; 1.3210x over previous
#include <cuda_runtime.h>
#include <cuda_bf16.h>
#include <stdint.h>

#define SEQ   2048
#define HID   768
#define NH    12
#define HD    64
#define BATCH 2
#define MROWS 4096   // BATCH*SEQ

// ---------------- device scratch (exact R2-passing set) --------------------
__device__ float g_qkv[3u * MROWS * HID];   // q | k | v fp32
__device__ float g_mrg[(size_t)MROWS * HID];
__device__ unsigned char g_mask[MROWS];

// ---------------- warp-MMA helpers (sm_80-era, valid on compute_100) -------
__device__ __forceinline__ uint32_t smem_u32(const void* p) {
    uint32_t a;
    asm("{ .reg .u64 t; cvta.to.shared.u64 t, %1; cvt.u32.u64 %0, t; }"
        : "=r"(a) : "l"(p));
    return a;
}
__device__ __forceinline__ void ldsm_x4(uint32_t& r0, uint32_t& r1,
                                        uint32_t& r2, uint32_t& r3, uint32_t a) {
    asm volatile("ldmatrix.sync.aligned.m8n8.x4.shared.b16 {%0,%1,%2,%3}, [%4];"
                 : "=r"(r0), "=r"(r1), "=r"(r2), "=r"(r3) : "r"(a));
}
__device__ __forceinline__ void mma_bf16(float& d0, float& d1, float& d2, float& d3,
                                         uint32_t a0, uint32_t a1, uint32_t a2,
                                         uint32_t a3, uint32_t b0, uint32_t b1) {
    asm volatile(
        "mma.sync.aligned.m16n8k16.row.col.f32.bf16.bf16.f32 "
        "{%0,%1,%2,%3}, {%4,%5,%6,%7}, {%8,%9}, {%0,%1,%2,%3};"
        : "+f"(d0), "+f"(d1), "+f"(d2), "+f"(d3)
        : "r"(a0), "r"(a1), "r"(a2), "r"(a3), "r"(b0), "r"(b1));
}
__device__ __forceinline__ uint32_t packbf(__nv_bfloat16 a, __nv_bfloat16 b) {
    return (uint32_t)__bfloat16_as_ushort(a)
         | ((uint32_t)__bfloat16_as_ushort(b) << 16);
}
// fp32x4 -> (hi bf16x4, lo bf16x4) packed as uint2 each
__device__ __forceinline__ void split4(float4 v, uint2& hi, uint2& lo) {
    __nv_bfloat16 hx = __float2bfloat16(v.x), hy = __float2bfloat16(v.y);
    __nv_bfloat16 hz = __float2bfloat16(v.z), hw = __float2bfloat16(v.w);
    hi.x = packbf(hx, hy);
    hi.y = packbf(hz, hw);
    lo.x = packbf(__float2bfloat16(v.x - __bfloat162float(hx)),
                  __float2bfloat16(v.y - __bfloat162float(hy)));
    lo.y = packbf(__float2bfloat16(v.z - __bfloat162float(hz)),
                  __float2bfloat16(v.w - __bfloat162float(hw)));
}

// ---------------------------------------------------------------------------
// prepass: decode bool mask stored as uint8 or int32  (unchanged from R2)
// ---------------------------------------------------------------------------
__global__ void decode_mask(const unsigned char* __restrict__ m, int n)
{
    __shared__ int nonz;
    if (threadIdx.x == 0) nonz = 0;
    __syncthreads();
    for (int i = threadIdx.x; i < n; i += blockDim.x)
        if ((i & 3) && m[i]) atomicOr(&nonz, 1);
    __syncthreads();
    const bool is_u8 = (nonz != 0);
    const int* mi = (const int*)m;
    for (int i = threadIdx.x; i < n; i += blockDim.x)
        g_mask[i] = is_u8 ? (m[i] != 0) : (mi[i] != 0);
}

// ---------------------------------------------------------------------------
// HMMA split-bf16 GEMM with INLINE fp32->bf16(hi/lo) conversion.
// C[4096,768] = A(M,K) * B(N,K)^T, fp32 in/out; internally
// C = Ah*Bh + Ah*Bl + Al*Bh (bf16 split, fp32 accum).
// CTA tile 128x64, 8 warps (4m x 2n), warp tile 32x32, K-chunk 32.
// blockIdx.z selects B0/B1/B2 and the g_qkv output slab (R2 interface).
// ---------------------------------------------------------------------------
#define KC     32
#define LDT    40            // smem row stride (bf16 elems), pad 32 -> 40
#define NCHUNK (HID / KC)    // 24

__global__ __launch_bounds__(256)
void tc_gemm(const float* __restrict__ A_ext, int a_from_mrg,
             const float* __restrict__ B0,
             const float* __restrict__ B1,
             const float* __restrict__ B2,
             float* __restrict__ C_ext, int c_to_qkv)
{
    __shared__ __nv_bfloat16 sAh[128 * LDT];
    __shared__ __nv_bfloat16 sAl[128 * LDT];
    __shared__ __nv_bfloat16 sBh[64 * LDT];
    __shared__ __nv_bfloat16 sBl[64 * LDT];

    const float* A = a_from_mrg ? (const float*)g_mrg : A_ext;
    const float* B = (blockIdx.z == 0) ? B0 : ((blockIdx.z == 1) ? B1 : B2);
    float* C = c_to_qkv ? (g_qkv + (size_t)blockIdx.z * MROWS * HID) : C_ext;

    const int tid = threadIdx.x;
    const int wid = tid >> 5;
    const int lane = tid & 31;
    const int bm = blockIdx.y * 128;
    const int bn = blockIdx.x * 64;
    const int m0 = (wid & 3) * 32;      // warp m origin (2 x m16)
    const int n0 = (wid >> 2) * 32;     // warp n origin (2 x n16)

    // ldmatrix lane patterns
    const int arow = lane & 15, acol = (lane >> 4) * 8;
    const int brow = (lane & 7) + ((lane >> 4) * 8), bcol = ((lane >> 3) & 1) * 8;

    const uint32_t uAh = smem_u32(sAh), uAl = smem_u32(sAl);
    const uint32_t uBh = smem_u32(sBh), uBl = smem_u32(sBl);

    float acc[2][4][4];
    #pragma unroll
    for (int i = 0; i < 2; i++)
        #pragma unroll
        for (int j = 0; j < 4; j++)
            #pragma unroll
            for (int q = 0; q < 4; q++) acc[i][j][q] = 0.f;

    for (int c = 0; c < NCHUNK; c++) {
        const int k0g = c * KC;
        __syncthreads();
        // A tile 128x32 fp32: 1024 float4 segs, 4 per thread; split inline.
        #pragma unroll
        for (int p = 0; p < 4; p++) {
            const int s = tid + p * 256;
            const int r = s >> 3, cc = (s & 7) * 4;
            float4 v = *(const float4*)(A + (size_t)(bm + r) * HID + k0g + cc);
            uint2 hi, lo;
            split4(v, hi, lo);
            *(uint2*)&sAh[r * LDT + cc] = hi;
            *(uint2*)&sAl[r * LDT + cc] = lo;
        }
        // B tile 64x32 fp32: 512 segs, 2 per thread.
        #pragma unroll
        for (int p = 0; p < 2; p++) {
            const int s = tid + p * 256;
            const int r = s >> 3, cc = (s & 7) * 4;
            float4 v = *(const float4*)(B + (size_t)(bn + r) * HID + k0g + cc);
            uint2 hi, lo;
            split4(v, hi, lo);
            *(uint2*)&sBh[r * LDT + cc] = hi;
            *(uint2*)&sBl[r * LDT + cc] = lo;
        }
        __syncthreads();

        #pragma unroll
        for (int ks = 0; ks < KC; ks += 16) {
            #pragma unroll
            for (int g = 0; g < 2; g++) {        // n16 group -> 2 n8 tiles
                uint32_t b0, b1, b2, b3, c0, c1, c2, c3;
                const uint32_t boff = ((n0 + g * 16 + brow) * LDT + ks + bcol) * 2;
                ldsm_x4(b0, b1, b2, b3, uBh + boff);
                ldsm_x4(c0, c1, c2, c3, uBl + boff);
                #pragma unroll
                for (int mt = 0; mt < 2; mt++) {
                    uint32_t h0, h1, h2, h3, l0, l1, l2, l3;
                    const uint32_t aoff = ((m0 + mt * 16 + arow) * LDT + ks + acol) * 2;
                    ldsm_x4(h0, h1, h2, h3, uAh + aoff);
                    ldsm_x4(l0, l1, l2, l3, uAl + aoff);
                    const int j0 = g * 2, j1 = g * 2 + 1;
                    mma_bf16(acc[mt][j0][0], acc[mt][j0][1], acc[mt][j0][2], acc[mt][j0][3],
                             h0, h1, h2, h3, b0, b1);
                    mma_bf16(acc[mt][j0][0], acc[mt][j0][1], acc[mt][j0][2], acc[mt][j0][3],
                             h0, h1, h2, h3, c0, c1);
                    mma_bf16(acc[mt][j0][0], acc[mt][j0][1], acc[mt][j0][2], acc[mt][j0][3],
                             l0, l1, l2, l3, b0, b1);
                    mma_bf16(acc[mt][j1][0], acc[mt][j1][1], acc[mt][j1][2], acc[mt][j1][3],
                             h0, h1, h2, h3, b2, b3);
                    mma_bf16(acc[mt][j1][0], acc[mt][j1][1], acc[mt][j1][2], acc[mt][j1][3],
                             h0, h1, h2, h3, c2, c3);
                    mma_bf16(acc[mt][j1][0], acc[mt][j1][1], acc[mt][j1][2], acc[mt][j1][3],
                             l0, l1, l2, l3, b2, b3);
                }
            }
        }
    }

    // epilogue: d0,d1 -> (row, col..col+1), d2,d3 -> (row+8, ...)
    const int erow = lane >> 2, ecol = (lane & 3) * 2;
    #pragma unroll
    for (int mt = 0; mt < 2; mt++) {
        #pragma unroll
        for (int ntile = 0; ntile < 4; ntile++) {
            size_t r = (size_t)(bm + m0 + mt * 16 + erow);
            int cc = bn + n0 + ntile * 8 + ecol;
            *(float2*)(C + r * HID + cc)       = make_float2(acc[mt][ntile][0], acc[mt][ntile][1]);
            *(float2*)(C + (r + 8) * HID + cc) = make_float2(acc[mt][ntile][2], acc[mt][ntile][3]);
        }
    }
}

// ---------------------------------------------------------------------------
// Flash attention (fp32 FFMA) — EXACT R2-passing version (writes fp32 g_mrg).
// ---------------------------------------------------------------------------
__global__ __launch_bounds__(256)
void attn_kernel()
{
    __shared__ float4 Qs4[64 * 16];
    __shared__ float4 KP4[64 * 16];
    __shared__ float4 Vs4[64 * 16];
    float* KPf = (float*)KP4;

    const int tid = threadIdx.x;
    const int tx = tid & 15;
    const int ty = tid >> 4;
    const int q0 = blockIdx.x * 64;
    const int b  = blockIdx.y / NH;
    const int h  = blockIdx.y % NH;

    const size_t base = (size_t)b * SEQ * HID + h * HD;
    const float* Qg = g_qkv + base;
    const float* Kg = g_qkv + (size_t)MROWS * HID + base;
    const float* Vg = g_qkv + 2ull * MROWS * HID + base;
    const unsigned char* mk = g_mask + b * SEQ;

    const int lrow0  = tid >> 4;
    const int lchunk = tid & 15;

    #pragma unroll
    for (int p = 0; p < 4; p++) {
        int r = p * 16 + lrow0;
        Qs4[r * 16 + lchunk] =
            *(const float4*)(Qg + (size_t)(q0 + r) * HID + lchunk * 4);
    }

    int row[4], scol[4];
    #pragma unroll
    for (int i = 0; i < 4; i++) row[i] = ty * 4 + i;
    #pragma unroll
    for (int j = 0; j < 4; j++) scol[j] = tx + 16 * j;

    float m_i[4], l_i[4], o[4][4];
    #pragma unroll
    for (int i = 0; i < 4; i++) {
        m_i[i] = -1e30f; l_i[i] = 0.f;
        #pragma unroll
        for (int j = 0; j < 4; j++) o[i][j] = 0.f;
    }

    for (int t = 0; t < SEQ / 64; t++) {
        const int kk0 = t * 64;
        __syncthreads();
        #pragma unroll
        for (int p = 0; p < 4; p++) {
            int r = p * 16 + lrow0;
            const size_t goff = (size_t)(kk0 + r) * HID + lchunk * 4;
            float4 kt = *(const float4*)(Kg + goff);
            float4 vt = *(const float4*)(Vg + goff);
            int sc = lchunk ^ (r & 15);
            KP4[r * 16 + sc] = kt;
            Vs4[r * 16 + sc] = vt;
        }
        __syncthreads();

        float bias[4];
        #pragma unroll
        for (int j = 0; j < 4; j++)
            bias[j] = mk[kk0 + scol[j]] ? 0.f : -1e30f;

        float s[4][4];
        #pragma unroll
        for (int i = 0; i < 4; i++)
            #pragma unroll
            for (int j = 0; j < 4; j++) s[i][j] = 0.f;

        #pragma unroll
        for (int cc = 0; cc < 16; cc++) {
            float4 aq[4], bk[4];
            #pragma unroll
            for (int i = 0; i < 4; i++) aq[i] = Qs4[row[i] * 16 + cc];
            #pragma unroll
            for (int j = 0; j < 4; j++) bk[j] = KP4[scol[j] * 16 + (cc ^ tx)];
            #pragma unroll
            for (int i = 0; i < 4; i++)
                #pragma unroll
                for (int j = 0; j < 4; j++) {
                    s[i][j] = fmaf(aq[i].x, bk[j].x, s[i][j]);
                    s[i][j] = fmaf(aq[i].y, bk[j].y, s[i][j]);
                    s[i][j] = fmaf(aq[i].z, bk[j].z, s[i][j]);
                    s[i][j] = fmaf(aq[i].w, bk[j].w, s[i][j]);
                }
        }

        #pragma unroll
        for (int i = 0; i < 4; i++) {
            float mt = m_i[i];
            #pragma unroll
            for (int j = 0; j < 4; j++) {
                s[i][j] = fmaf(s[i][j], 0.125f, bias[j]);
                mt = fmaxf(mt, s[i][j]);
            }
            #pragma unroll
            for (int w = 1; w < 16; w <<= 1)
                mt = fmaxf(mt, __shfl_xor_sync(0xffffffffu, mt, w));
            float alpha = __expf(m_i[i] - mt);
            float rs = 0.f;
            #pragma unroll
            for (int j = 0; j < 4; j++) {
                s[i][j] = __expf(s[i][j] - mt);
                rs += s[i][j];
            }
            #pragma unroll
            for (int w = 1; w < 16; w <<= 1)
                rs += __shfl_xor_sync(0xffffffffu, rs, w);
            l_i[i] = l_i[i] * alpha + rs;
            m_i[i] = mt;
            #pragma unroll
            for (int j = 0; j < 4; j++) o[i][j] *= alpha;
        }

        __syncthreads();
        #pragma unroll
        for (int i = 0; i < 4; i++)
            #pragma unroll
            for (int j = 0; j < 4; j++)
                KPf[row[i] * 64 + scol[j]] = s[i][j];
        __syncthreads();

        #pragma unroll
        for (int c4 = 0; c4 < 16; c4++) {
            float4 pr[4];
            #pragma unroll
            for (int i = 0; i < 4; i++)
                pr[i] = ((const float4*)KPf)[row[i] * 16 + c4];
            #pragma unroll
            for (int u = 0; u < 4; u++) {
                int kv = c4 * 4 + u;
                float4 vv = Vs4[kv * 16 + (tx ^ (kv & 15))];
                #pragma unroll
                for (int i = 0; i < 4; i++) {
                    float p = ((const float*)&pr[i])[u];
                    o[i][0] = fmaf(p, vv.x, o[i][0]);
                    o[i][1] = fmaf(p, vv.y, o[i][1]);
                    o[i][2] = fmaf(p, vv.z, o[i][2]);
                    o[i][3] = fmaf(p, vv.w, o[i][3]);
                }
            }
        }
    }

    #pragma unroll
    for (int i = 0; i < 4; i++) {
        float inv = 1.f / l_i[i];
        float4 r4 = make_float4(o[i][0] * inv, o[i][1] * inv,
                                o[i][2] * inv, o[i][3] * inv);
        *(float4*)(g_mrg + (size_t)(b * SEQ + q0 + row[i]) * HID + h * HD + tx * 4) = r4;
    }
}

// ---------------------------------------------------------------------------
extern "C" void kernel_launch(void* const* d_in, const int* in_sizes, int n_in,
                              void* d_out, int out_size)
{
    const float*         x    = (const float*)d_in[0];
    const unsigned char* mask = (const unsigned char*)d_in[1];
    const float*         Wq   = (const float*)d_in[2];
    const float*         Wk   = (const float*)d_in[3];
    const float*         Wv   = (const float*)d_in[4];
    const float*         Wp   = (const float*)d_in[5];
    float*               out  = (float*)d_out;

    dim3 blk(256);
    decode_mask<<<1, 256>>>(mask, in_sizes[1]);
    // QKV projections on tensor cores (HMMA, inline bf16 split)
    tc_gemm<<<dim3(HID / 64, MROWS / 128, 3), blk>>>(x, 0, Wq, Wk, Wv, nullptr, 1);
    // Attention (fp32)
    attn_kernel<<<dim3(SEQ / 64, BATCH * NH), blk>>>();
    // Output projection on tensor cores
    tc_gemm<<<dim3(HID / 64, MROWS / 128, 1), blk>>>(nullptr, 1, Wp, Wp, Wp, out, 0);
}

// round 9
// speedup vs baseline: 2.3450x; 1.7753x over previous
#include <cuda_runtime.h>
#include <cuda_bf16.h>
#include <stdint.h>

#define SEQ   2048
#define HID   768
#define NH    12
#define HD    64
#define BATCH 2
#define MROWS 4096   // BATCH*SEQ

// ---------------- device scratch -------------------------------------------
__device__ float g_qkv[3u * MROWS * HID];   // q | k | v fp32
__device__ float g_mrg[(size_t)MROWS * HID];
__device__ unsigned char g_mask[MROWS];

// ---------------- warp-MMA helpers (sm_80-era, valid on compute_100) -------
__device__ __forceinline__ uint32_t smem_u32(const void* p) {
    uint32_t a;
    asm("{ .reg .u64 t; cvta.to.shared.u64 t, %1; cvt.u32.u64 %0, t; }"
        : "=r"(a) : "l"(p));
    return a;
}
__device__ __forceinline__ void ldsm_x4(uint32_t& r0, uint32_t& r1,
                                        uint32_t& r2, uint32_t& r3, uint32_t a) {
    asm volatile("ldmatrix.sync.aligned.m8n8.x4.shared.b16 {%0,%1,%2,%3}, [%4];"
                 : "=r"(r0), "=r"(r1), "=r"(r2), "=r"(r3) : "r"(a));
}
__device__ __forceinline__ void ldsm_x4_t(uint32_t& r0, uint32_t& r1,
                                          uint32_t& r2, uint32_t& r3, uint32_t a) {
    asm volatile("ldmatrix.sync.aligned.m8n8.x4.trans.shared.b16 {%0,%1,%2,%3}, [%4];"
                 : "=r"(r0), "=r"(r1), "=r"(r2), "=r"(r3) : "r"(a));
}
__device__ __forceinline__ void mma_bf16(float& d0, float& d1, float& d2, float& d3,
                                         uint32_t a0, uint32_t a1, uint32_t a2,
                                         uint32_t a3, uint32_t b0, uint32_t b1) {
    asm volatile(
        "mma.sync.aligned.m16n8k16.row.col.f32.bf16.bf16.f32 "
        "{%0,%1,%2,%3}, {%4,%5,%6,%7}, {%8,%9}, {%0,%1,%2,%3};"
        : "+f"(d0), "+f"(d1), "+f"(d2), "+f"(d3)
        : "r"(a0), "r"(a1), "r"(a2), "r"(a3), "r"(b0), "r"(b1));
}
__device__ __forceinline__ uint32_t packbf(__nv_bfloat16 a, __nv_bfloat16 b) {
    return (uint32_t)__bfloat16_as_ushort(a)
         | ((uint32_t)__bfloat16_as_ushort(b) << 16);
}
__device__ __forceinline__ void split4(float4 v, uint2& hi, uint2& lo) {
    __nv_bfloat16 hx = __float2bfloat16(v.x), hy = __float2bfloat16(v.y);
    __nv_bfloat16 hz = __float2bfloat16(v.z), hw = __float2bfloat16(v.w);
    hi.x = packbf(hx, hy);
    hi.y = packbf(hz, hw);
    lo.x = packbf(__float2bfloat16(v.x - __bfloat162float(hx)),
                  __float2bfloat16(v.y - __bfloat162float(hy)));
    lo.y = packbf(__float2bfloat16(v.z - __bfloat162float(hz)),
                  __float2bfloat16(v.w - __bfloat162float(hw)));
}
// split a single fp32 softmax weight into hi/lo bf16
__device__ __forceinline__ void splitp(float v, __nv_bfloat16& h, __nv_bfloat16& l) {
    h = __float2bfloat16(v);
    l = __float2bfloat16(v - __bfloat162float(h));
}
// swizzled element offset in a 64-wide bf16 row tile
__device__ __forceinline__ int swz(int row, int col) {
    return row * 64 + (((col >> 3) ^ (row & 7)) << 3) + (col & 7);
}

// ---------------------------------------------------------------------------
// prepass: decode bool mask stored as uint8 or int32
// ---------------------------------------------------------------------------
__global__ void decode_mask(const unsigned char* __restrict__ m, int n)
{
    __shared__ int nonz;
    if (threadIdx.x == 0) nonz = 0;
    __syncthreads();
    for (int i = threadIdx.x; i < n; i += blockDim.x)
        if ((i & 3) && m[i]) atomicOr(&nonz, 1);
    __syncthreads();
    const bool is_u8 = (nonz != 0);
    const int* mi = (const int*)m;
    for (int i = threadIdx.x; i < n; i += blockDim.x)
        g_mask[i] = is_u8 ? (m[i] != 0) : (mi[i] != 0);
}

// ---------------------------------------------------------------------------
// HMMA split-bf16 GEMM (unchanged from R8 pass): C = A * B^T, inline split.
// ---------------------------------------------------------------------------
#define KC     32
#define LDT    40
#define NCHUNK (HID / KC)

__global__ __launch_bounds__(256)
void tc_gemm(const float* __restrict__ A_ext, int a_from_mrg,
             const float* __restrict__ B0,
             const float* __restrict__ B1,
             const float* __restrict__ B2,
             float* __restrict__ C_ext, int c_to_qkv)
{
    __shared__ __nv_bfloat16 sAh[128 * LDT];
    __shared__ __nv_bfloat16 sAl[128 * LDT];
    __shared__ __nv_bfloat16 sBh[64 * LDT];
    __shared__ __nv_bfloat16 sBl[64 * LDT];

    const float* A = a_from_mrg ? (const float*)g_mrg : A_ext;
    const float* B = (blockIdx.z == 0) ? B0 : ((blockIdx.z == 1) ? B1 : B2);
    float* C = c_to_qkv ? (g_qkv + (size_t)blockIdx.z * MROWS * HID) : C_ext;

    const int tid = threadIdx.x;
    const int wid = tid >> 5;
    const int lane = tid & 31;
    const int bm = blockIdx.y * 128;
    const int bn = blockIdx.x * 64;
    const int m0 = (wid & 3) * 32;
    const int n0 = (wid >> 2) * 32;

    const int arow = lane & 15, acol = (lane >> 4) * 8;
    const int brow = (lane & 7) + ((lane >> 4) * 8), bcol = ((lane >> 3) & 1) * 8;

    const uint32_t uAh = smem_u32(sAh), uAl = smem_u32(sAl);
    const uint32_t uBh = smem_u32(sBh), uBl = smem_u32(sBl);

    float acc[2][4][4];
    #pragma unroll
    for (int i = 0; i < 2; i++)
        #pragma unroll
        for (int j = 0; j < 4; j++)
            #pragma unroll
            for (int q = 0; q < 4; q++) acc[i][j][q] = 0.f;

    for (int c = 0; c < NCHUNK; c++) {
        const int k0g = c * KC;
        __syncthreads();
        #pragma unroll
        for (int p = 0; p < 4; p++) {
            const int s = tid + p * 256;
            const int r = s >> 3, cc = (s & 7) * 4;
            float4 v = *(const float4*)(A + (size_t)(bm + r) * HID + k0g + cc);
            uint2 hi, lo;
            split4(v, hi, lo);
            *(uint2*)&sAh[r * LDT + cc] = hi;
            *(uint2*)&sAl[r * LDT + cc] = lo;
        }
        #pragma unroll
        for (int p = 0; p < 2; p++) {
            const int s = tid + p * 256;
            const int r = s >> 3, cc = (s & 7) * 4;
            float4 v = *(const float4*)(B + (size_t)(bn + r) * HID + k0g + cc);
            uint2 hi, lo;
            split4(v, hi, lo);
            *(uint2*)&sBh[r * LDT + cc] = hi;
            *(uint2*)&sBl[r * LDT + cc] = lo;
        }
        __syncthreads();

        #pragma unroll
        for (int ks = 0; ks < KC; ks += 16) {
            #pragma unroll
            for (int g = 0; g < 2; g++) {
                uint32_t b0, b1, b2, b3, c0, c1, c2, c3;
                const uint32_t boff = ((n0 + g * 16 + brow) * LDT + ks + bcol) * 2;
                ldsm_x4(b0, b1, b2, b3, uBh + boff);
                ldsm_x4(c0, c1, c2, c3, uBl + boff);
                #pragma unroll
                for (int mt = 0; mt < 2; mt++) {
                    uint32_t h0, h1, h2, h3, l0, l1, l2, l3;
                    const uint32_t aoff = ((m0 + mt * 16 + arow) * LDT + ks + acol) * 2;
                    ldsm_x4(h0, h1, h2, h3, uAh + aoff);
                    ldsm_x4(l0, l1, l2, l3, uAl + aoff);
                    const int j0 = g * 2, j1 = g * 2 + 1;
                    mma_bf16(acc[mt][j0][0], acc[mt][j0][1], acc[mt][j0][2], acc[mt][j0][3],
                             h0, h1, h2, h3, b0, b1);
                    mma_bf16(acc[mt][j0][0], acc[mt][j0][1], acc[mt][j0][2], acc[mt][j0][3],
                             h0, h1, h2, h3, c0, c1);
                    mma_bf16(acc[mt][j0][0], acc[mt][j0][1], acc[mt][j0][2], acc[mt][j0][3],
                             l0, l1, l2, l3, b0, b1);
                    mma_bf16(acc[mt][j1][0], acc[mt][j1][1], acc[mt][j1][2], acc[mt][j1][3],
                             h0, h1, h2, h3, b2, b3);
                    mma_bf16(acc[mt][j1][0], acc[mt][j1][1], acc[mt][j1][2], acc[mt][j1][3],
                             h0, h1, h2, h3, c2, c3);
                    mma_bf16(acc[mt][j1][0], acc[mt][j1][1], acc[mt][j1][2], acc[mt][j1][3],
                             l0, l1, l2, l3, b2, b3);
                }
            }
        }
    }

    const int erow = lane >> 2, ecol = (lane & 3) * 2;
    #pragma unroll
    for (int mt = 0; mt < 2; mt++) {
        #pragma unroll
        for (int ntile = 0; ntile < 4; ntile++) {
            size_t r = (size_t)(bm + m0 + mt * 16 + erow);
            int cc = bn + n0 + ntile * 8 + ecol;
            *(float2*)(C + r * HID + cc)       = make_float2(acc[mt][ntile][0], acc[mt][ntile][1]);
            *(float2*)(C + (r + 8) * HID + cc) = make_float2(acc[mt][ntile][2], acc[mt][ntile][3]);
        }
    }
}

// ---------------------------------------------------------------------------
// HMMA flash attention. CTA = (b, h, 128-row q tile), 8 warps, warp = m16
// rows (softmax fully in-warp). Split-bf16 for QK^T and PV (3 products).
// Q/K/V tiles in swizzled smem (hi/lo); V^T B-frags via ldmatrix.trans.
// Dynamic smem: Q 2x16KB + K 2x8KB + V 2x8KB + bias = 65792 B.
// ---------------------------------------------------------------------------
#define ATTN_SMEM 65792

__global__ __launch_bounds__(256)
void attn_mma()
{
    extern __shared__ char dynsm[];
    __nv_bfloat16* sQh = (__nv_bfloat16*)dynsm;
    __nv_bfloat16* sQl = sQh + 8192;
    __nv_bfloat16* sKh = sQl + 8192;
    __nv_bfloat16* sKl = sKh + 4096;
    __nv_bfloat16* sVh = sKl + 4096;
    __nv_bfloat16* sVl = sVh + 4096;
    float* sBias = (float*)(sVl + 4096);

    const int tid = threadIdx.x;
    const int w = tid >> 5;
    const int lane = tid & 31;
    const int q0 = blockIdx.x * 128;
    const int b = blockIdx.y / NH;
    const int h = blockIdx.y % NH;

    const size_t base = (size_t)b * SEQ * HID + h * HD;
    const float* Qg = g_qkv + base;
    const float* Kg = g_qkv + (size_t)MROWS * HID + base;
    const float* Vg = g_qkv + 2ull * MROWS * HID + base;
    const unsigned char* mk = g_mask + b * SEQ;

    // ---- load Q tile (128x64), split, swizzled ----
    #pragma unroll
    for (int p = 0; p < 8; p++) {
        const int s = p * 256 + tid;
        const int r = s >> 4, c = (s & 15) * 4;
        float4 v = *(const float4*)(Qg + (size_t)(q0 + r) * HID + c);
        uint2 hi, lo;
        split4(v, hi, lo);
        const int off = swz(r, c);
        *(uint2*)(sQh + off) = hi;
        *(uint2*)(sQl + off) = lo;
    }

    const uint32_t uQh = smem_u32(sQh), uQl = smem_u32(sQl);
    const uint32_t uKh = smem_u32(sKh), uKl = smem_u32(sKl);
    const uint32_t uVh = smem_u32(sVh), uVl = smem_u32(sVl);

    const int m0 = w * 16;
    const int arow = m0 + (lane & 15);
    const int acolb = (lane >> 4) << 3;
    const int browp = (lane & 7) + ((lane >> 4) << 3);   // K B-frag row pattern
    const int bcolp = ((lane >> 3) & 1) << 3;            // K B-frag col pattern
    const int vrowp = (lane & 7) + (((lane >> 3) & 1) << 3); // V-trans row pattern
    const int vcolp = ((lane >> 4) & 1) << 3;                // V-trans col pattern
    const int ecol2 = (lane & 3) * 2;

    float mr0 = -1e30f, mr1 = -1e30f, lr0 = 0.f, lr1 = 0.f;
    float o[8][4];
    #pragma unroll
    for (int j = 0; j < 8; j++)
        #pragma unroll
        for (int q = 0; q < 4; q++) o[j][q] = 0.f;

    for (int t = 0; t < SEQ / 64; t++) {
        __syncthreads();
        // ---- load K, V tiles (64x64 each), split, swizzled ----
        #pragma unroll
        for (int p = 0; p < 4; p++) {
            const int s = p * 256 + tid;
            const int r = s >> 4, c = (s & 15) * 4;
            const size_t goff = (size_t)(t * 64 + r) * HID + c;
            uint2 hi, lo;
            float4 kv = *(const float4*)(Kg + goff);
            split4(kv, hi, lo);
            const int off = swz(r, c);
            *(uint2*)(sKh + off) = hi;
            *(uint2*)(sKl + off) = lo;
            float4 vv = *(const float4*)(Vg + goff);
            split4(vv, hi, lo);
            *(uint2*)(sVh + off) = hi;
            *(uint2*)(sVl + off) = lo;
        }
        if (tid < 64) sBias[tid] = mk[t * 64 + tid] ? 0.f : -1e30f;
        __syncthreads();

        // ---- S = Q * K^T (split-bf16, 3 products) ----
        float s_[8][4];
        #pragma unroll
        for (int j = 0; j < 8; j++)
            #pragma unroll
            for (int q = 0; q < 4; q++) s_[j][q] = 0.f;

        #pragma unroll
        for (int ks = 0; ks < 4; ks++) {
            uint32_t h0, h1, h2, h3, l0, l1, l2, l3;
            const uint32_t aoff = (uint32_t)swz(arow, ks * 16 + acolb) * 2;
            ldsm_x4(h0, h1, h2, h3, uQh + aoff);
            ldsm_x4(l0, l1, l2, l3, uQl + aoff);
            #pragma unroll
            for (int g = 0; g < 4; g++) {
                uint32_t kb0, kb1, kb2, kb3, kc0, kc1, kc2, kc3;
                const uint32_t boff =
                    (uint32_t)swz(g * 16 + browp, ks * 16 + bcolp) * 2;
                ldsm_x4(kb0, kb1, kb2, kb3, uKh + boff);
                ldsm_x4(kc0, kc1, kc2, kc3, uKl + boff);
                const int j0 = g * 2, j1 = g * 2 + 1;
                mma_bf16(s_[j0][0], s_[j0][1], s_[j0][2], s_[j0][3], h0, h1, h2, h3, kb0, kb1);
                mma_bf16(s_[j0][0], s_[j0][1], s_[j0][2], s_[j0][3], h0, h1, h2, h3, kc0, kc1);
                mma_bf16(s_[j0][0], s_[j0][1], s_[j0][2], s_[j0][3], l0, l1, l2, l3, kb0, kb1);
                mma_bf16(s_[j1][0], s_[j1][1], s_[j1][2], s_[j1][3], h0, h1, h2, h3, kb2, kb3);
                mma_bf16(s_[j1][0], s_[j1][1], s_[j1][2], s_[j1][3], h0, h1, h2, h3, kc2, kc3);
                mma_bf16(s_[j1][0], s_[j1][1], s_[j1][2], s_[j1][3], l0, l1, l2, l3, kb2, kb3);
            }
        }

        // ---- online softmax (rows fully in-warp) ----
        float mx0 = -1e30f, mx1 = -1e30f;
        #pragma unroll
        for (int j = 0; j < 8; j++) {
            const float b0 = sBias[j * 8 + ecol2];
            const float b1 = sBias[j * 8 + ecol2 + 1];
            s_[j][0] = fmaf(s_[j][0], 0.125f, b0);
            s_[j][1] = fmaf(s_[j][1], 0.125f, b1);
            s_[j][2] = fmaf(s_[j][2], 0.125f, b0);
            s_[j][3] = fmaf(s_[j][3], 0.125f, b1);
            mx0 = fmaxf(mx0, fmaxf(s_[j][0], s_[j][1]));
            mx1 = fmaxf(mx1, fmaxf(s_[j][2], s_[j][3]));
        }
        #pragma unroll
        for (int d = 1; d < 4; d <<= 1) {
            mx0 = fmaxf(mx0, __shfl_xor_sync(0xffffffffu, mx0, d));
            mx1 = fmaxf(mx1, __shfl_xor_sync(0xffffffffu, mx1, d));
        }
        const float mn0 = fmaxf(mr0, mx0);
        const float mn1 = fmaxf(mr1, mx1);
        const float al0 = __expf(mr0 - mn0);
        const float al1 = __expf(mr1 - mn1);
        mr0 = mn0; mr1 = mn1;

        float rs0 = 0.f, rs1 = 0.f;
        #pragma unroll
        for (int j = 0; j < 8; j++) {
            s_[j][0] = __expf(s_[j][0] - mn0);
            s_[j][1] = __expf(s_[j][1] - mn0);
            s_[j][2] = __expf(s_[j][2] - mn1);
            s_[j][3] = __expf(s_[j][3] - mn1);
            rs0 += s_[j][0] + s_[j][1];
            rs1 += s_[j][2] + s_[j][3];
        }
        #pragma unroll
        for (int d = 1; d < 4; d <<= 1) {
            rs0 += __shfl_xor_sync(0xffffffffu, rs0, d);
            rs1 += __shfl_xor_sync(0xffffffffu, rs1, d);
        }
        lr0 = lr0 * al0 + rs0;
        lr1 = lr1 * al1 + rs1;
        #pragma unroll
        for (int j = 0; j < 8; j++) {
            o[j][0] *= al0; o[j][1] *= al0;
            o[j][2] *= al1; o[j][3] *= al1;
        }

        // ---- O += P * V (split-bf16; P acc-frags -> A-frags directly) ----
        #pragma unroll
        for (int kf = 0; kf < 4; kf++) {
            __nv_bfloat16 ph[8], pl[8];
            splitp(s_[2 * kf][0], ph[0], pl[0]);
            splitp(s_[2 * kf][1], ph[1], pl[1]);
            splitp(s_[2 * kf][2], ph[2], pl[2]);
            splitp(s_[2 * kf][3], ph[3], pl[3]);
            splitp(s_[2 * kf + 1][0], ph[4], pl[4]);
            splitp(s_[2 * kf + 1][1], ph[5], pl[5]);
            splitp(s_[2 * kf + 1][2], ph[6], pl[6]);
            splitp(s_[2 * kf + 1][3], ph[7], pl[7]);
            const uint32_t ah0 = packbf(ph[0], ph[1]), ah1 = packbf(ph[2], ph[3]);
            const uint32_t ah2 = packbf(ph[4], ph[5]), ah3 = packbf(ph[6], ph[7]);
            const uint32_t am0 = packbf(pl[0], pl[1]), am1 = packbf(pl[2], pl[3]);
            const uint32_t am2 = packbf(pl[4], pl[5]), am3 = packbf(pl[6], pl[7]);
            #pragma unroll
            for (int g = 0; g < 4; g++) {
                uint32_t v0, v1, v2, v3, u0, u1, u2, u3;
                const uint32_t voff =
                    (uint32_t)swz(kf * 16 + vrowp, g * 16 + vcolp) * 2;
                ldsm_x4_t(v0, v1, v2, v3, uVh + voff);
                ldsm_x4_t(u0, u1, u2, u3, uVl + voff);
                const int d0 = g * 2, d1 = g * 2 + 1;
                mma_bf16(o[d0][0], o[d0][1], o[d0][2], o[d0][3], ah0, ah1, ah2, ah3, v0, v1);
                mma_bf16(o[d0][0], o[d0][1], o[d0][2], o[d0][3], ah0, ah1, ah2, ah3, u0, u1);
                mma_bf16(o[d0][0], o[d0][1], o[d0][2], o[d0][3], am0, am1, am2, am3, v0, v1);
                mma_bf16(o[d1][0], o[d1][1], o[d1][2], o[d1][3], ah0, ah1, ah2, ah3, v2, v3);
                mma_bf16(o[d1][0], o[d1][1], o[d1][2], o[d1][3], ah0, ah1, ah2, ah3, u2, u3);
                mma_bf16(o[d1][0], o[d1][1], o[d1][2], o[d1][3], am0, am1, am2, am3, v2, v3);
            }
        }
    }

    // ---- epilogue: normalize, write merged [b*SEQ+s][HID] fp32 ----
    const float inv0 = 1.f / lr0;
    const float inv1 = 1.f / lr1;
    const int erow = lane >> 2;
    const size_t r0g = (size_t)(b * SEQ + q0 + m0 + erow) * HID + h * HD;
    const size_t r1g = r0g + 8 * HID;
    #pragma unroll
    for (int dt = 0; dt < 8; dt++) {
        const int cc = dt * 8 + ecol2;
        *(float2*)(g_mrg + r0g + cc) = make_float2(o[dt][0] * inv0, o[dt][1] * inv0);
        *(float2*)(g_mrg + r1g + cc) = make_float2(o[dt][2] * inv1, o[dt][3] * inv1);
    }
}

// ---------------------------------------------------------------------------
extern "C" void kernel_launch(void* const* d_in, const int* in_sizes, int n_in,
                              void* d_out, int out_size)
{
    const float*         x    = (const float*)d_in[0];
    const unsigned char* mask = (const unsigned char*)d_in[1];
    const float*         Wq   = (const float*)d_in[2];
    const float*         Wk   = (const float*)d_in[3];
    const float*         Wv   = (const float*)d_in[4];
    const float*         Wp   = (const float*)d_in[5];
    float*               out  = (float*)d_out;

    cudaFuncSetAttribute(attn_mma, cudaFuncAttributeMaxDynamicSharedMemorySize,
                         ATTN_SMEM);

    dim3 blk(256);
    decode_mask<<<1, 256>>>(mask, in_sizes[1]);
    // QKV projections on tensor cores (HMMA, inline bf16 split)
    tc_gemm<<<dim3(HID / 64, MROWS / 128, 3), blk>>>(x, 0, Wq, Wk, Wv, nullptr, 1);
    // Attention on tensor cores
    attn_mma<<<dim3(SEQ / 128, BATCH * NH), blk, ATTN_SMEM>>>();
    // Output projection on tensor cores
    tc_gemm<<<dim3(HID / 64, MROWS / 128, 1), blk>>>(nullptr, 1, Wp, Wp, Wp, out, 0);
}

// round 10
// speedup vs baseline: 2.7031x; 1.1527x over previous
#include <cuda_runtime.h>
#include <cuda_bf16.h>
#include <stdint.h>

#define SEQ   2048
#define HID   768
#define NH    12
#define HD    64
#define BATCH 2
#define MROWS 4096   // BATCH*SEQ

// ---------------- device scratch (keep total ~50MB like passing R9) --------
__device__ float g_q[(size_t)MROWS * HID];          // Q fp32
__device__ float g_mrg[(size_t)MROWS * HID];        // merged attn out fp32
__device__ __nv_bfloat16 g_kh[(size_t)MROWS * HID]; // K hi/lo bf16
__device__ __nv_bfloat16 g_kl[(size_t)MROWS * HID];
__device__ __nv_bfloat16 g_vh[(size_t)MROWS * HID]; // V hi/lo bf16
__device__ __nv_bfloat16 g_vl[(size_t)MROWS * HID];
__device__ unsigned char g_mask[MROWS];

// ---------------- warp-MMA / async helpers ---------------------------------
__device__ __forceinline__ uint32_t smem_u32(const void* p) {
    uint32_t a;
    asm("{ .reg .u64 t; cvta.to.shared.u64 t, %1; cvt.u32.u64 %0, t; }"
        : "=r"(a) : "l"(p));
    return a;
}
__device__ __forceinline__ void ldsm_x4(uint32_t& r0, uint32_t& r1,
                                        uint32_t& r2, uint32_t& r3, uint32_t a) {
    asm volatile("ldmatrix.sync.aligned.m8n8.x4.shared.b16 {%0,%1,%2,%3}, [%4];"
                 : "=r"(r0), "=r"(r1), "=r"(r2), "=r"(r3) : "r"(a));
}
__device__ __forceinline__ void ldsm_x4_t(uint32_t& r0, uint32_t& r1,
                                          uint32_t& r2, uint32_t& r3, uint32_t a) {
    asm volatile("ldmatrix.sync.aligned.m8n8.x4.trans.shared.b16 {%0,%1,%2,%3}, [%4];"
                 : "=r"(r0), "=r"(r1), "=r"(r2), "=r"(r3) : "r"(a));
}
__device__ __forceinline__ void mma_bf16(float& d0, float& d1, float& d2, float& d3,
                                         uint32_t a0, uint32_t a1, uint32_t a2,
                                         uint32_t a3, uint32_t b0, uint32_t b1) {
    asm volatile(
        "mma.sync.aligned.m16n8k16.row.col.f32.bf16.bf16.f32 "
        "{%0,%1,%2,%3}, {%4,%5,%6,%7}, {%8,%9}, {%0,%1,%2,%3};"
        : "+f"(d0), "+f"(d1), "+f"(d2), "+f"(d3)
        : "r"(a0), "r"(a1), "r"(a2), "r"(a3), "r"(b0), "r"(b1));
}
__device__ __forceinline__ void cp16(uint32_t s, const void* g) {
    asm volatile("cp.async.cg.shared.global [%0], [%1], 16;"
                 :: "r"(s), "l"(g) : "memory");
}
#define CP_COMMIT() asm volatile("cp.async.commit_group;" ::: "memory")
#define CP_WAIT0()  asm volatile("cp.async.wait_group 0;" ::: "memory")

__device__ __forceinline__ uint32_t packbf(__nv_bfloat16 a, __nv_bfloat16 b) {
    return (uint32_t)__bfloat16_as_ushort(a)
         | ((uint32_t)__bfloat16_as_ushort(b) << 16);
}
__device__ __forceinline__ void split4(float4 v, uint2& hi, uint2& lo) {
    __nv_bfloat16 hx = __float2bfloat16(v.x), hy = __float2bfloat16(v.y);
    __nv_bfloat16 hz = __float2bfloat16(v.z), hw = __float2bfloat16(v.w);
    hi.x = packbf(hx, hy);
    hi.y = packbf(hz, hw);
    lo.x = packbf(__float2bfloat16(v.x - __bfloat162float(hx)),
                  __float2bfloat16(v.y - __bfloat162float(hy)));
    lo.y = packbf(__float2bfloat16(v.z - __bfloat162float(hz)),
                  __float2bfloat16(v.w - __bfloat162float(hw)));
}
__device__ __forceinline__ void splitp(float v, __nv_bfloat16& h, __nv_bfloat16& l) {
    h = __float2bfloat16(v);
    l = __float2bfloat16(v - __bfloat162float(h));
}
// swizzled element offset in a 64-wide bf16 row tile
__device__ __forceinline__ int swz(int row, int col) {
    return row * 64 + (((col >> 3) ^ (row & 7)) << 3) + (col & 7);
}

// ---------------------------------------------------------------------------
// prepass: decode bool mask stored as uint8 or int32
// ---------------------------------------------------------------------------
__global__ void decode_mask(const unsigned char* __restrict__ m, int n)
{
    __shared__ int nonz;
    if (threadIdx.x == 0) nonz = 0;
    __syncthreads();
    for (int i = threadIdx.x; i < n; i += blockDim.x)
        if ((i & 3) && m[i]) atomicOr(&nonz, 1);
    __syncthreads();
    const bool is_u8 = (nonz != 0);
    const int* mi = (const int*)m;
    for (int i = threadIdx.x; i < n; i += blockDim.x)
        g_mask[i] = is_u8 ? (m[i] != 0) : (mi[i] != 0);
}

// ---------------------------------------------------------------------------
// HMMA split-bf16 GEMM: C = A * B^T, inline fp32->bf16 split, register-
// prefetch pipelined (chunk c+1 loads issued before chunk c MMAs).
// mode 0: z=0 -> g_q fp32; z=1 -> g_kh/g_kl bf16; z=2 -> g_vh/g_vl bf16.
// mode 1: C_ext fp32 (B = B0 = Wp).
// ---------------------------------------------------------------------------
#define KC     32
#define LDT    40
#define NCHUNK (HID / KC)

__global__ __launch_bounds__(256)
void tc_gemm(const float* __restrict__ A_ext, int a_from_mrg,
             const float* __restrict__ B0,
             const float* __restrict__ B1,
             const float* __restrict__ B2,
             float* __restrict__ C_ext, int mode)
{
    __shared__ __nv_bfloat16 sAh[128 * LDT];
    __shared__ __nv_bfloat16 sAl[128 * LDT];
    __shared__ __nv_bfloat16 sBh[64 * LDT];
    __shared__ __nv_bfloat16 sBl[64 * LDT];

    const float* A = a_from_mrg ? (const float*)g_mrg : A_ext;
    const float* B = (blockIdx.z == 0) ? B0 : ((blockIdx.z == 1) ? B1 : B2);

    const int tid = threadIdx.x;
    const int wid = tid >> 5;
    const int lane = tid & 31;
    const int bm = blockIdx.y * 128;
    const int bn = blockIdx.x * 64;
    const int m0 = (wid & 3) * 32;
    const int n0 = (wid >> 2) * 32;

    const int arow = lane & 15, acol = (lane >> 4) * 8;
    const int brow = (lane & 7) + ((lane >> 4) * 8), bcol = ((lane >> 3) & 1) * 8;

    const uint32_t uAh = smem_u32(sAh), uAl = smem_u32(sAl);
    const uint32_t uBh = smem_u32(sBh), uBl = smem_u32(sBl);

    float acc[2][4][4];
    #pragma unroll
    for (int i = 0; i < 2; i++)
        #pragma unroll
        for (int j = 0; j < 4; j++)
            #pragma unroll
            for (int q = 0; q < 4; q++) acc[i][j][q] = 0.f;

    float4 av[4], bv[2];
    auto ldA = [&](int c) {
        #pragma unroll
        for (int p = 0; p < 4; p++) {
            const int s = tid + p * 256;
            const int r = s >> 3, cc = (s & 7) * 4;
            av[p] = *(const float4*)(A + (size_t)(bm + r) * HID + c * KC + cc);
        }
    };
    auto ldB = [&](int c) {
        #pragma unroll
        for (int p = 0; p < 2; p++) {
            const int s = tid + p * 256;
            const int r = s >> 3, cc = (s & 7) * 4;
            bv[p] = *(const float4*)(B + (size_t)(bn + r) * HID + c * KC + cc);
        }
    };

    ldA(0); ldB(0);

    for (int c = 0; c < NCHUNK; c++) {
        __syncthreads();
        #pragma unroll
        for (int p = 0; p < 4; p++) {
            const int s = tid + p * 256;
            const int r = s >> 3, cc = (s & 7) * 4;
            uint2 hi, lo;
            split4(av[p], hi, lo);
            *(uint2*)&sAh[r * LDT + cc] = hi;
            *(uint2*)&sAl[r * LDT + cc] = lo;
        }
        #pragma unroll
        for (int p = 0; p < 2; p++) {
            const int s = tid + p * 256;
            const int r = s >> 3, cc = (s & 7) * 4;
            uint2 hi, lo;
            split4(bv[p], hi, lo);
            *(uint2*)&sBh[r * LDT + cc] = hi;
            *(uint2*)&sBl[r * LDT + cc] = lo;
        }
        __syncthreads();
        if (c + 1 < NCHUNK) { ldA(c + 1); ldB(c + 1); }

        #pragma unroll
        for (int ks = 0; ks < KC; ks += 16) {
            #pragma unroll
            for (int g = 0; g < 2; g++) {
                uint32_t b0, b1, b2, b3, c0, c1, c2, c3;
                const uint32_t boff = ((n0 + g * 16 + brow) * LDT + ks + bcol) * 2;
                ldsm_x4(b0, b1, b2, b3, uBh + boff);
                ldsm_x4(c0, c1, c2, c3, uBl + boff);
                #pragma unroll
                for (int mt = 0; mt < 2; mt++) {
                    uint32_t h0, h1, h2, h3, l0, l1, l2, l3;
                    const uint32_t aoff = ((m0 + mt * 16 + arow) * LDT + ks + acol) * 2;
                    ldsm_x4(h0, h1, h2, h3, uAh + aoff);
                    ldsm_x4(l0, l1, l2, l3, uAl + aoff);
                    const int j0 = g * 2, j1 = g * 2 + 1;
                    mma_bf16(acc[mt][j0][0], acc[mt][j0][1], acc[mt][j0][2], acc[mt][j0][3],
                             h0, h1, h2, h3, b0, b1);
                    mma_bf16(acc[mt][j0][0], acc[mt][j0][1], acc[mt][j0][2], acc[mt][j0][3],
                             h0, h1, h2, h3, c0, c1);
                    mma_bf16(acc[mt][j0][0], acc[mt][j0][1], acc[mt][j0][2], acc[mt][j0][3],
                             l0, l1, l2, l3, b0, b1);
                    mma_bf16(acc[mt][j1][0], acc[mt][j1][1], acc[mt][j1][2], acc[mt][j1][3],
                             h0, h1, h2, h3, b2, b3);
                    mma_bf16(acc[mt][j1][0], acc[mt][j1][1], acc[mt][j1][2], acc[mt][j1][3],
                             h0, h1, h2, h3, c2, c3);
                    mma_bf16(acc[mt][j1][0], acc[mt][j1][1], acc[mt][j1][2], acc[mt][j1][3],
                             l0, l1, l2, l3, b2, b3);
                }
            }
        }
    }

    const int erow = lane >> 2, ecol = (lane & 3) * 2;
    if (mode == 1 || blockIdx.z == 0) {
        float* C = (mode == 1) ? C_ext : g_q;
        #pragma unroll
        for (int mt = 0; mt < 2; mt++) {
            #pragma unroll
            for (int nt = 0; nt < 4; nt++) {
                size_t r = (size_t)(bm + m0 + mt * 16 + erow);
                int cc = bn + n0 + nt * 8 + ecol;
                *(float2*)(C + r * HID + cc)       = make_float2(acc[mt][nt][0], acc[mt][nt][1]);
                *(float2*)(C + (r + 8) * HID + cc) = make_float2(acc[mt][nt][2], acc[mt][nt][3]);
            }
        }
    } else {
        __nv_bfloat16* Dh = (blockIdx.z == 1) ? g_kh : g_vh;
        __nv_bfloat16* Dl = (blockIdx.z == 1) ? g_kl : g_vl;
        #pragma unroll
        for (int mt = 0; mt < 2; mt++) {
            #pragma unroll
            for (int nt = 0; nt < 4; nt++) {
                size_t r = (size_t)(bm + m0 + mt * 16 + erow);
                int cc = bn + n0 + nt * 8 + ecol;
                __nv_bfloat16 h0, l0, h1, l1;
                splitp(acc[mt][nt][0], h0, l0);
                splitp(acc[mt][nt][1], h1, l1);
                *(uint32_t*)(Dh + r * HID + cc) = packbf(h0, h1);
                *(uint32_t*)(Dl + r * HID + cc) = packbf(l0, l1);
                splitp(acc[mt][nt][2], h0, l0);
                splitp(acc[mt][nt][3], h1, l1);
                *(uint32_t*)(Dh + (r + 8) * HID + cc) = packbf(h0, h1);
                *(uint32_t*)(Dl + (r + 8) * HID + cc) = packbf(l0, l1);
            }
        }
    }
}

// ---------------------------------------------------------------------------
// HMMA flash attention, cp.async double-buffered K/V (pre-split bf16 hi/lo).
// CTA = (b, h, 128-row q tile), 8 warps, warp = m16 rows.
// smem: Q hi/lo 32KB | 2 stages x (Kh,Kl,Vh,Vl 8KB each) 64KB | bias 256B.
// ---------------------------------------------------------------------------
#define STAGE_B   32768
#define ATTN_SMEM (32768 + 2 * STAGE_B + 256)

__global__ __launch_bounds__(256)
void attn_mma()
{
    extern __shared__ char dynsm[];
    const uint32_t uS  = smem_u32(dynsm);
    const uint32_t uQh = uS, uQl = uS + 16384;
    const uint32_t uKV = uS + 32768;
    float* sBias = (float*)(dynsm + 32768 + 2 * STAGE_B);

    const int tid = threadIdx.x;
    const int w = tid >> 5;
    const int lane = tid & 31;
    const int q0 = blockIdx.x * 128;
    const int b = blockIdx.y / NH;
    const int h = blockIdx.y % NH;

    const size_t base = (size_t)b * SEQ * HID + h * HD;
    const float* Qg = g_q + base;
    const __nv_bfloat16* Khg = g_kh + base;
    const __nv_bfloat16* Klg = g_kl + base;
    const __nv_bfloat16* Vhg = g_vh + base;
    const __nv_bfloat16* Vlg = g_vl + base;
    const unsigned char* mk = g_mask + b * SEQ;

    // per-thread cp.async geometry: 16B seg = (row, 8 bf16 cols)
    const int cr  = tid >> 3;           // 0..31 (+32 with p)
    const int cc8 = (tid & 7) * 8;

    // prologue: stage 0 <- tile 0
    #pragma unroll
    for (int p = 0; p < 2; p++) {
        const int r = cr + p * 32;
        const size_t go = (size_t)r * HID + cc8;
        const uint32_t so = (uint32_t)swz(r, cc8) * 2;
        cp16(uKV + so,          Khg + go);
        cp16(uKV + 8192 + so,   Klg + go);
        cp16(uKV + 16384 + so,  Vhg + go);
        cp16(uKV + 24576 + so,  Vlg + go);
    }
    CP_COMMIT();

    // Q tile (128x64) load + split + swizzle (overlaps the async K/V load)
    #pragma unroll
    for (int p = 0; p < 8; p++) {
        const int s = p * 256 + tid;
        const int r = s >> 4, c = (s & 15) * 4;
        float4 v = *(const float4*)(Qg + (size_t)(q0 + r) * HID + c);
        uint2 hi, lo;
        split4(v, hi, lo);
        const int off2 = swz(r, c) * 2;
        *(uint2*)(dynsm + off2)         = hi;
        *(uint2*)(dynsm + 16384 + off2) = lo;
    }

    const int m0 = w * 16;
    const int arow = m0 + (lane & 15);
    const int acolb = (lane >> 4) << 3;
    const int browp = (lane & 7) + ((lane >> 4) << 3);
    const int bcolp = ((lane >> 3) & 1) << 3;
    const int vrowp = (lane & 7) + (((lane >> 3) & 1) << 3);
    const int vcolp = ((lane >> 4) & 1) << 3;
    const int ecol2 = (lane & 3) * 2;

    float mr0 = -1e30f, mr1 = -1e30f, lr0 = 0.f, lr1 = 0.f;
    float o[8][4];
    #pragma unroll
    for (int j = 0; j < 8; j++)
        #pragma unroll
        for (int q = 0; q < 4; q++) o[j][q] = 0.f;

    for (int t = 0; t < SEQ / 64; t++) {
        const int buf = t & 1;
        CP_WAIT0();
        __syncthreads();     // stage buf ready; all warps done with t-1

        if (tid < 64) sBias[tid] = mk[t * 64 + tid] ? 0.f : -1e30f;
        if (t + 1 < SEQ / 64) {
            const uint32_t dst = uKV + (buf ^ 1) * STAGE_B;
            #pragma unroll
            for (int p = 0; p < 2; p++) {
                const int r = cr + p * 32;
                const size_t go = (size_t)((t + 1) * 64 + r) * HID + cc8;
                const uint32_t so = (uint32_t)swz(r, cc8) * 2;
                cp16(dst + so,          Khg + go);
                cp16(dst + 8192 + so,   Klg + go);
                cp16(dst + 16384 + so,  Vhg + go);
                cp16(dst + 24576 + so,  Vlg + go);
            }
        }
        CP_COMMIT();
        __syncthreads();     // bias visible

        const uint32_t uKh = uKV + buf * STAGE_B;
        const uint32_t uKl = uKh + 8192;
        const uint32_t uVh = uKh + 16384;
        const uint32_t uVl = uKh + 24576;

        // ---- S = Q * K^T (split-bf16, 3 products) ----
        float s_[8][4];
        #pragma unroll
        for (int j = 0; j < 8; j++)
            #pragma unroll
            for (int q = 0; q < 4; q++) s_[j][q] = 0.f;

        #pragma unroll
        for (int ks = 0; ks < 4; ks++) {
            uint32_t h0, h1, h2, h3, l0, l1, l2, l3;
            const uint32_t aoff = (uint32_t)swz(arow, ks * 16 + acolb) * 2;
            ldsm_x4(h0, h1, h2, h3, uQh + aoff);
            ldsm_x4(l0, l1, l2, l3, uQl + aoff);
            #pragma unroll
            for (int g = 0; g < 4; g++) {
                uint32_t kb0, kb1, kb2, kb3, kc0, kc1, kc2, kc3;
                const uint32_t boff =
                    (uint32_t)swz(g * 16 + browp, ks * 16 + bcolp) * 2;
                ldsm_x4(kb0, kb1, kb2, kb3, uKh + boff);
                ldsm_x4(kc0, kc1, kc2, kc3, uKl + boff);
                const int j0 = g * 2, j1 = g * 2 + 1;
                mma_bf16(s_[j0][0], s_[j0][1], s_[j0][2], s_[j0][3], h0, h1, h2, h3, kb0, kb1);
                mma_bf16(s_[j0][0], s_[j0][1], s_[j0][2], s_[j0][3], h0, h1, h2, h3, kc0, kc1);
                mma_bf16(s_[j0][0], s_[j0][1], s_[j0][2], s_[j0][3], l0, l1, l2, l3, kb0, kb1);
                mma_bf16(s_[j1][0], s_[j1][1], s_[j1][2], s_[j1][3], h0, h1, h2, h3, kb2, kb3);
                mma_bf16(s_[j1][0], s_[j1][1], s_[j1][2], s_[j1][3], h0, h1, h2, h3, kc2, kc3);
                mma_bf16(s_[j1][0], s_[j1][1], s_[j1][2], s_[j1][3], l0, l1, l2, l3, kb2, kb3);
            }
        }

        // ---- online softmax (rows fully in-warp) ----
        float mx0 = -1e30f, mx1 = -1e30f;
        #pragma unroll
        for (int j = 0; j < 8; j++) {
            const float b0 = sBias[j * 8 + ecol2];
            const float b1 = sBias[j * 8 + ecol2 + 1];
            s_[j][0] = fmaf(s_[j][0], 0.125f, b0);
            s_[j][1] = fmaf(s_[j][1], 0.125f, b1);
            s_[j][2] = fmaf(s_[j][2], 0.125f, b0);
            s_[j][3] = fmaf(s_[j][3], 0.125f, b1);
            mx0 = fmaxf(mx0, fmaxf(s_[j][0], s_[j][1]));
            mx1 = fmaxf(mx1, fmaxf(s_[j][2], s_[j][3]));
        }
        #pragma unroll
        for (int d = 1; d < 4; d <<= 1) {
            mx0 = fmaxf(mx0, __shfl_xor_sync(0xffffffffu, mx0, d));
            mx1 = fmaxf(mx1, __shfl_xor_sync(0xffffffffu, mx1, d));
        }
        const float mn0 = fmaxf(mr0, mx0);
        const float mn1 = fmaxf(mr1, mx1);
        const float al0 = __expf(mr0 - mn0);
        const float al1 = __expf(mr1 - mn1);
        mr0 = mn0; mr1 = mn1;

        float rs0 = 0.f, rs1 = 0.f;
        #pragma unroll
        for (int j = 0; j < 8; j++) {
            s_[j][0] = __expf(s_[j][0] - mn0);
            s_[j][1] = __expf(s_[j][1] - mn0);
            s_[j][2] = __expf(s_[j][2] - mn1);
            s_[j][3] = __expf(s_[j][3] - mn1);
            rs0 += s_[j][0] + s_[j][1];
            rs1 += s_[j][2] + s_[j][3];
        }
        #pragma unroll
        for (int d = 1; d < 4; d <<= 1) {
            rs0 += __shfl_xor_sync(0xffffffffu, rs0, d);
            rs1 += __shfl_xor_sync(0xffffffffu, rs1, d);
        }
        lr0 = lr0 * al0 + rs0;
        lr1 = lr1 * al1 + rs1;
        #pragma unroll
        for (int j = 0; j < 8; j++) {
            o[j][0] *= al0; o[j][1] *= al0;
            o[j][2] *= al1; o[j][3] *= al1;
        }

        // ---- O += P * V (split-bf16; P acc-frags -> A-frags directly) ----
        #pragma unroll
        for (int kf = 0; kf < 4; kf++) {
            __nv_bfloat16 ph[8], pl[8];
            splitp(s_[2 * kf][0], ph[0], pl[0]);
            splitp(s_[2 * kf][1], ph[1], pl[1]);
            splitp(s_[2 * kf][2], ph[2], pl[2]);
            splitp(s_[2 * kf][3], ph[3], pl[3]);
            splitp(s_[2 * kf + 1][0], ph[4], pl[4]);
            splitp(s_[2 * kf + 1][1], ph[5], pl[5]);
            splitp(s_[2 * kf + 1][2], ph[6], pl[6]);
            splitp(s_[2 * kf + 1][3], ph[7], pl[7]);
            const uint32_t ah0 = packbf(ph[0], ph[1]), ah1 = packbf(ph[2], ph[3]);
            const uint32_t ah2 = packbf(ph[4], ph[5]), ah3 = packbf(ph[6], ph[7]);
            const uint32_t am0 = packbf(pl[0], pl[1]), am1 = packbf(pl[2], pl[3]);
            const uint32_t am2 = packbf(pl[4], pl[5]), am3 = packbf(pl[6], pl[7]);
            #pragma unroll
            for (int g = 0; g < 4; g++) {
                uint32_t v0, v1, v2, v3, u0, u1, u2, u3;
                const uint32_t voff =
                    (uint32_t)swz(kf * 16 + vrowp, g * 16 + vcolp) * 2;
                ldsm_x4_t(v0, v1, v2, v3, uVh + voff);
                ldsm_x4_t(u0, u1, u2, u3, uVl + voff);
                const int d0 = g * 2, d1 = g * 2 + 1;
                mma_bf16(o[d0][0], o[d0][1], o[d0][2], o[d0][3], ah0, ah1, ah2, ah3, v0, v1);
                mma_bf16(o[d0][0], o[d0][1], o[d0][2], o[d0][3], ah0, ah1, ah2, ah3, u0, u1);
                mma_bf16(o[d0][0], o[d0][1], o[d0][2], o[d0][3], am0, am1, am2, am3, v0, v1);
                mma_bf16(o[d1][0], o[d1][1], o[d1][2], o[d1][3], ah0, ah1, ah2, ah3, v2, v3);
                mma_bf16(o[d1][0], o[d1][1], o[d1][2], o[d1][3], ah0, ah1, ah2, ah3, u2, u3);
                mma_bf16(o[d1][0], o[d1][1], o[d1][2], o[d1][3], am0, am1, am2, am3, v2, v3);
            }
        }
    }

    // ---- epilogue: normalize, write merged [b*SEQ+s][HID] fp32 ----
    const float inv0 = 1.f / lr0;
    const float inv1 = 1.f / lr1;
    const int erow = lane >> 2;
    const size_t r0g = (size_t)(b * SEQ + q0 + m0 + erow) * HID + h * HD;
    const size_t r1g = r0g + 8 * HID;
    #pragma unroll
    for (int dt = 0; dt < 8; dt++) {
        const int cc = dt * 8 + ecol2;
        *(float2*)(g_mrg + r0g + cc) = make_float2(o[dt][0] * inv0, o[dt][1] * inv0);
        *(float2*)(g_mrg + r1g + cc) = make_float2(o[dt][2] * inv1, o[dt][3] * inv1);
    }
}

// ---------------------------------------------------------------------------
extern "C" void kernel_launch(void* const* d_in, const int* in_sizes, int n_in,
                              void* d_out, int out_size)
{
    const float*         x    = (const float*)d_in[0];
    const unsigned char* mask = (const unsigned char*)d_in[1];
    const float*         Wq   = (const float*)d_in[2];
    const float*         Wk   = (const float*)d_in[3];
    const float*         Wv   = (const float*)d_in[4];
    const float*         Wp   = (const float*)d_in[5];
    float*               out  = (float*)d_out;

    cudaFuncSetAttribute(attn_mma, cudaFuncAttributeMaxDynamicSharedMemorySize,
                         ATTN_SMEM);

    dim3 blk(256);
    decode_mask<<<1, 256>>>(mask, in_sizes[1]);
    // QKV projections (Q -> fp32, K/V -> pre-split bf16 hi/lo)
    tc_gemm<<<dim3(HID / 64, MROWS / 128, 3), blk>>>(x, 0, Wq, Wk, Wv, nullptr, 0);
    // Attention on tensor cores, cp.async double-buffered K/V
    attn_mma<<<dim3(SEQ / 128, BATCH * NH), blk, ATTN_SMEM>>>();
    // Output projection
    tc_gemm<<<dim3(HID / 64, MROWS / 128, 1), blk>>>(nullptr, 1, Wp, Wp, Wp, out, 1);
}

// round 12
// speedup vs baseline: 2.7729x; 1.0258x over previous
#include <cuda_runtime.h>
#include <cuda_bf16.h>
#include <stdint.h>

#define SEQ   2048
#define HID   768
#define NH    12
#define HD    64
#define BATCH 2
#define MROWS 4096   // BATCH*SEQ

// ---------------- device scratch -------------------------------------------
__device__ float g_q[(size_t)MROWS * HID];          // Q fp32
__device__ float g_mrg[(size_t)MROWS * HID];        // merged attn out fp32
__device__ __nv_bfloat16 g_kh[(size_t)MROWS * HID]; // K hi/lo bf16
__device__ __nv_bfloat16 g_kl[(size_t)MROWS * HID];
__device__ __nv_bfloat16 g_vh[(size_t)MROWS * HID]; // V hi/lo bf16
__device__ __nv_bfloat16 g_vl[(size_t)MROWS * HID];
__device__ unsigned char g_mask[MROWS];

// ---------------- warp-MMA / async helpers ---------------------------------
__device__ __forceinline__ uint32_t smem_u32(const void* p) {
    uint32_t a;
    asm("{ .reg .u64 t; cvta.to.shared.u64 t, %1; cvt.u32.u64 %0, t; }"
        : "=r"(a) : "l"(p));
    return a;
}
__device__ __forceinline__ void ldsm_x4(uint32_t& r0, uint32_t& r1,
                                        uint32_t& r2, uint32_t& r3, uint32_t a) {
    asm volatile("ldmatrix.sync.aligned.m8n8.x4.shared.b16 {%0,%1,%2,%3}, [%4];"
                 : "=r"(r0), "=r"(r1), "=r"(r2), "=r"(r3) : "r"(a));
}
__device__ __forceinline__ void ldsm_x4_t(uint32_t& r0, uint32_t& r1,
                                          uint32_t& r2, uint32_t& r3, uint32_t a) {
    asm volatile("ldmatrix.sync.aligned.m8n8.x4.trans.shared.b16 {%0,%1,%2,%3}, [%4];"
                 : "=r"(r0), "=r"(r1), "=r"(r2), "=r"(r3) : "r"(a));
}
__device__ __forceinline__ void mma_bf16(float& d0, float& d1, float& d2, float& d3,
                                         uint32_t a0, uint32_t a1, uint32_t a2,
                                         uint32_t a3, uint32_t b0, uint32_t b1) {
    asm volatile(
        "mma.sync.aligned.m16n8k16.row.col.f32.bf16.bf16.f32 "
        "{%0,%1,%2,%3}, {%4,%5,%6,%7}, {%8,%9}, {%0,%1,%2,%3};"
        : "+f"(d0), "+f"(d1), "+f"(d2), "+f"(d3)
        : "r"(a0), "r"(a1), "r"(a2), "r"(a3), "r"(b0), "r"(b1));
}
__device__ __forceinline__ void cp16(uint32_t s, const void* g) {
    asm volatile("cp.async.cg.shared.global [%0], [%1], 16;"
                 :: "r"(s), "l"(g) : "memory");
}
#define CP_COMMIT() asm volatile("cp.async.commit_group;" ::: "memory")
#define CP_WAIT0()  asm volatile("cp.async.wait_group 0;" ::: "memory")

__device__ __forceinline__ uint32_t packbf(__nv_bfloat16 a, __nv_bfloat16 b) {
    return (uint32_t)__bfloat16_as_ushort(a)
         | ((uint32_t)__bfloat16_as_ushort(b) << 16);
}
__device__ __forceinline__ void split4(float4 v, uint2& hi, uint2& lo) {
    __nv_bfloat16 hx = __float2bfloat16(v.x), hy = __float2bfloat16(v.y);
    __nv_bfloat16 hz = __float2bfloat16(v.z), hw = __float2bfloat16(v.w);
    hi.x = packbf(hx, hy);
    hi.y = packbf(hz, hw);
    lo.x = packbf(__float2bfloat16(v.x - __bfloat162float(hx)),
                  __float2bfloat16(v.y - __bfloat162float(hy)));
    lo.y = packbf(__float2bfloat16(v.z - __bfloat162float(hz)),
                  __float2bfloat16(v.w - __bfloat162float(hw)));
}
__device__ __forceinline__ void splitp(float v, __nv_bfloat16& h, __nv_bfloat16& l) {
    h = __float2bfloat16(v);
    l = __float2bfloat16(v - __bfloat162float(h));
}
// swizzled element offset in a 64-wide bf16 row tile
__device__ __forceinline__ int swz(int row, int col) {
    return row * 64 + (((col >> 3) ^ (row & 7)) << 3) + (col & 7);
}

// ---------------------------------------------------------------------------
// prepass: decode bool mask stored as uint8 or int32
// ---------------------------------------------------------------------------
__global__ void decode_mask(const unsigned char* __restrict__ m, int n)
{
    __shared__ int nonz;
    if (threadIdx.x == 0) nonz = 0;
    __syncthreads();
    for (int i = threadIdx.x; i < n; i += blockDim.x)
        if ((i & 3) && m[i]) atomicOr(&nonz, 1);
    __syncthreads();
    const bool is_u8 = (nonz != 0);
    const int* mi = (const int*)m;
    for (int i = threadIdx.x; i < n; i += blockDim.x)
        g_mask[i] = is_u8 ? (m[i] != 0) : (mi[i] != 0);
}

// ---------------------------------------------------------------------------
// HMMA split-bf16 GEMM: C = A * B^T, inline fp32->bf16 split.
// CTA 128x64, 8 warps, warp 32x32, K-chunk 64 (half the syncs of KC=32).
// Dynamic smem (55296 B > 48KB static cap): sAh|sAl|sBh|sBl.
// mode 0: z=0 -> g_q fp32; z=1 -> g_kh/g_kl bf16; z=2 -> g_vh/g_vl bf16.
// mode 1: C_ext fp32 (B = B0 = Wp).
// ---------------------------------------------------------------------------
#define KC     64
#define LDT    72            // 64 cols + 8 pad: 16B/row phase shift, LDSM-clean
#define NCHUNK (HID / KC)    // 12
#define GA_H   0
#define GA_L   (128 * LDT)
#define GB_H   (2 * 128 * LDT)
#define GB_L   (2 * 128 * LDT + 64 * LDT)
#define GEMM_SMEM ((2 * 128 * LDT + 2 * 64 * LDT) * 2)   // 55296 B

__global__ __launch_bounds__(256)
void tc_gemm(const float* __restrict__ A_ext, int a_from_mrg,
             const float* __restrict__ B0,
             const float* __restrict__ B1,
             const float* __restrict__ B2,
             float* __restrict__ C_ext, int mode)
{
    extern __shared__ __nv_bfloat16 gsm[];
    __nv_bfloat16* sAh = gsm + GA_H;
    __nv_bfloat16* sAl = gsm + GA_L;
    __nv_bfloat16* sBh = gsm + GB_H;
    __nv_bfloat16* sBl = gsm + GB_L;

    const float* A = a_from_mrg ? (const float*)g_mrg : A_ext;
    const float* B = (blockIdx.z == 0) ? B0 : ((blockIdx.z == 1) ? B1 : B2);

    const int tid = threadIdx.x;
    const int wid = tid >> 5;
    const int lane = tid & 31;
    const int bm = blockIdx.y * 128;
    const int bn = blockIdx.x * 64;
    const int m0 = (wid & 3) * 32;
    const int n0 = (wid >> 2) * 32;

    const int arow = lane & 15, acol = (lane >> 4) * 8;
    const int brow = (lane & 7) + ((lane >> 4) * 8), bcol = ((lane >> 3) & 1) * 8;

    const uint32_t uAh = smem_u32(sAh), uAl = smem_u32(sAl);
    const uint32_t uBh = smem_u32(sBh), uBl = smem_u32(sBl);

    float acc[2][4][4];
    #pragma unroll
    for (int i = 0; i < 2; i++)
        #pragma unroll
        for (int j = 0; j < 4; j++)
            #pragma unroll
            for (int q = 0; q < 4; q++) acc[i][j][q] = 0.f;

    for (int c = 0; c < NCHUNK; c++) {
        const int k0g = c * KC;
        __syncthreads();
        // A tile 128x64 fp32: 2048 float4 segs -> 8/thread
        #pragma unroll
        for (int p = 0; p < 8; p++) {
            const int s = tid + p * 256;
            const int r = s >> 4, cc = (s & 15) * 4;
            float4 v = *(const float4*)(A + (size_t)(bm + r) * HID + k0g + cc);
            uint2 hi, lo;
            split4(v, hi, lo);
            *(uint2*)&sAh[r * LDT + cc] = hi;
            *(uint2*)&sAl[r * LDT + cc] = lo;
        }
        // B tile 64x64 fp32: 1024 segs -> 4/thread
        #pragma unroll
        for (int p = 0; p < 4; p++) {
            const int s = tid + p * 256;
            const int r = s >> 4, cc = (s & 15) * 4;
            float4 v = *(const float4*)(B + (size_t)(bn + r) * HID + k0g + cc);
            uint2 hi, lo;
            split4(v, hi, lo);
            *(uint2*)&sBh[r * LDT + cc] = hi;
            *(uint2*)&sBl[r * LDT + cc] = lo;
        }
        __syncthreads();

        #pragma unroll
        for (int ks = 0; ks < KC; ks += 16) {
            #pragma unroll
            for (int g = 0; g < 2; g++) {
                uint32_t b0, b1, b2, b3, c0, c1, c2, c3;
                const uint32_t boff = ((n0 + g * 16 + brow) * LDT + ks + bcol) * 2;
                ldsm_x4(b0, b1, b2, b3, uBh + boff);
                ldsm_x4(c0, c1, c2, c3, uBl + boff);
                #pragma unroll
                for (int mt = 0; mt < 2; mt++) {
                    uint32_t h0, h1, h2, h3, l0, l1, l2, l3;
                    const uint32_t aoff = ((m0 + mt * 16 + arow) * LDT + ks + acol) * 2;
                    ldsm_x4(h0, h1, h2, h3, uAh + aoff);
                    ldsm_x4(l0, l1, l2, l3, uAl + aoff);
                    const int j0 = g * 2, j1 = g * 2 + 1;
                    mma_bf16(acc[mt][j0][0], acc[mt][j0][1], acc[mt][j0][2], acc[mt][j0][3],
                             h0, h1, h2, h3, b0, b1);
                    mma_bf16(acc[mt][j0][0], acc[mt][j0][1], acc[mt][j0][2], acc[mt][j0][3],
                             h0, h1, h2, h3, c0, c1);
                    mma_bf16(acc[mt][j0][0], acc[mt][j0][1], acc[mt][j0][2], acc[mt][j0][3],
                             l0, l1, l2, l3, b0, b1);
                    mma_bf16(acc[mt][j1][0], acc[mt][j1][1], acc[mt][j1][2], acc[mt][j1][3],
                             h0, h1, h2, h3, b2, b3);
                    mma_bf16(acc[mt][j1][0], acc[mt][j1][1], acc[mt][j1][2], acc[mt][j1][3],
                             h0, h1, h2, h3, c2, c3);
                    mma_bf16(acc[mt][j1][0], acc[mt][j1][1], acc[mt][j1][2], acc[mt][j1][3],
                             l0, l1, l2, l3, b2, b3);
                }
            }
        }
    }

    const int erow = lane >> 2, ecol = (lane & 3) * 2;
    if (mode == 1 || blockIdx.z == 0) {
        float* C = (mode == 1) ? C_ext : g_q;
        #pragma unroll
        for (int mt = 0; mt < 2; mt++) {
            #pragma unroll
            for (int nt = 0; nt < 4; nt++) {
                size_t r = (size_t)(bm + m0 + mt * 16 + erow);
                int cc = bn + n0 + nt * 8 + ecol;
                *(float2*)(C + r * HID + cc)       = make_float2(acc[mt][nt][0], acc[mt][nt][1]);
                *(float2*)(C + (r + 8) * HID + cc) = make_float2(acc[mt][nt][2], acc[mt][nt][3]);
            }
        }
    } else {
        __nv_bfloat16* Dh = (blockIdx.z == 1) ? g_kh : g_vh;
        __nv_bfloat16* Dl = (blockIdx.z == 1) ? g_kl : g_vl;
        #pragma unroll
        for (int mt = 0; mt < 2; mt++) {
            #pragma unroll
            for (int nt = 0; nt < 4; nt++) {
                size_t r = (size_t)(bm + m0 + mt * 16 + erow);
                int cc = bn + n0 + nt * 8 + ecol;
                __nv_bfloat16 h0, l0, h1, l1;
                splitp(acc[mt][nt][0], h0, l0);
                splitp(acc[mt][nt][1], h1, l1);
                *(uint32_t*)(Dh + r * HID + cc) = packbf(h0, h1);
                *(uint32_t*)(Dl + r * HID + cc) = packbf(l0, l1);
                splitp(acc[mt][nt][2], h0, l0);
                splitp(acc[mt][nt][3], h1, l1);
                *(uint32_t*)(Dh + (r + 8) * HID + cc) = packbf(h0, h1);
                *(uint32_t*)(Dl + (r + 8) * HID + cc) = packbf(l0, l1);
            }
        }
    }
}

// ---------------------------------------------------------------------------
// HMMA flash attention, cp.async double-buffered K/V (pre-split bf16 hi/lo).
// Full-row mask bias preloaded once; ONE __syncthreads per kv tile.
// smem: Q hi/lo 32KB | 2 stages x 32KB | bias 8KB = 104.25KB -> 2 CTAs/SM.
// ---------------------------------------------------------------------------
#define STAGE_B   32768
#define ATTN_SMEM (32768 + 2 * STAGE_B + SEQ * 4)

__global__ __launch_bounds__(256)
void attn_mma()
{
    extern __shared__ char dynsm[];
    const uint32_t uS  = smem_u32(dynsm);
    const uint32_t uQh = uS, uQl = uS + 16384;
    const uint32_t uKV = uS + 32768;
    float* sBias = (float*)(dynsm + 32768 + 2 * STAGE_B);

    const int tid = threadIdx.x;
    const int w = tid >> 5;
    const int lane = tid & 31;
    const int q0 = blockIdx.x * 128;
    const int b = blockIdx.y / NH;
    const int h = blockIdx.y % NH;

    const size_t base = (size_t)b * SEQ * HID + h * HD;
    const float* Qg = g_q + base;
    const __nv_bfloat16* Khg = g_kh + base;
    const __nv_bfloat16* Klg = g_kl + base;
    const __nv_bfloat16* Vhg = g_vh + base;
    const __nv_bfloat16* Vlg = g_vl + base;
    const unsigned char* mk = g_mask + b * SEQ;

    // per-thread cp.async geometry: 16B seg = (row, 8 bf16 cols)
    const int cr  = tid >> 3;           // 0..31 (+32 with p)
    const int cc8 = (tid & 7) * 8;

    // prologue: stage 0 <- tile 0
    #pragma unroll
    for (int p = 0; p < 2; p++) {
        const int r = cr + p * 32;
        const size_t go = (size_t)r * HID + cc8;
        const uint32_t so = (uint32_t)swz(r, cc8) * 2;
        cp16(uKV + so,          Khg + go);
        cp16(uKV + 8192 + so,   Klg + go);
        cp16(uKV + 16384 + so,  Vhg + go);
        cp16(uKV + 24576 + so,  Vlg + go);
    }
    CP_COMMIT();

    // Q tile (128x64) load + split + swizzle, and full mask-bias preload
    #pragma unroll
    for (int p = 0; p < 8; p++) {
        const int s = p * 256 + tid;
        const int r = s >> 4, c = (s & 15) * 4;
        float4 v = *(const float4*)(Qg + (size_t)(q0 + r) * HID + c);
        uint2 hi, lo;
        split4(v, hi, lo);
        const int off2 = swz(r, c) * 2;
        *(uint2*)(dynsm + off2)         = hi;
        *(uint2*)(dynsm + 16384 + off2) = lo;
    }
    #pragma unroll
    for (int p = 0; p < SEQ / 256; p++) {
        const int i = p * 256 + tid;
        sBias[i] = mk[i] ? 0.f : -1e30f;
    }

    const int m0 = w * 16;
    const int arow = m0 + (lane & 15);
    const int acolb = (lane >> 4) << 3;
    const int browp = (lane & 7) + ((lane >> 4) << 3);
    const int bcolp = ((lane >> 3) & 1) << 3;
    const int vrowp = (lane & 7) + (((lane >> 3) & 1) << 3);
    const int vcolp = ((lane >> 4) & 1) << 3;
    const int ecol2 = (lane & 3) * 2;

    float mr0 = -1e30f, mr1 = -1e30f, lr0 = 0.f, lr1 = 0.f;
    float o[8][4];
    #pragma unroll
    for (int j = 0; j < 8; j++)
        #pragma unroll
        for (int q = 0; q < 4; q++) o[j][q] = 0.f;

    for (int t = 0; t < SEQ / 64; t++) {
        const int buf = t & 1;
        CP_WAIT0();
        __syncthreads();     // stage buf ready; all warps done with buf^1

        if (t + 1 < SEQ / 64) {
            const uint32_t dst = uKV + (buf ^ 1) * STAGE_B;
            #pragma unroll
            for (int p = 0; p < 2; p++) {
                const int r = cr + p * 32;
                const size_t go = (size_t)((t + 1) * 64 + r) * HID + cc8;
                const uint32_t so = (uint32_t)swz(r, cc8) * 2;
                cp16(dst + so,          Khg + go);
                cp16(dst + 8192 + so,   Klg + go);
                cp16(dst + 16384 + so,  Vhg + go);
                cp16(dst + 24576 + so,  Vlg + go);
            }
        }
        CP_COMMIT();

        const uint32_t uKh = uKV + buf * STAGE_B;
        const uint32_t uKl = uKh + 8192;
        const uint32_t uVh = uKh + 16384;
        const uint32_t uVl = uKh + 24576;
        const float* bias = sBias + t * 64;

        // ---- S = Q * K^T (split-bf16, 3 products) ----
        float s_[8][4];
        #pragma unroll
        for (int j = 0; j < 8; j++)
            #pragma unroll
            for (int q = 0; q < 4; q++) s_[j][q] = 0.f;

        #pragma unroll
        for (int ks = 0; ks < 4; ks++) {
            uint32_t h0, h1, h2, h3, l0, l1, l2, l3;
            const uint32_t aoff = (uint32_t)swz(arow, ks * 16 + acolb) * 2;
            ldsm_x4(h0, h1, h2, h3, uQh + aoff);
            ldsm_x4(l0, l1, l2, l3, uQl + aoff);
            #pragma unroll
            for (int g = 0; g < 4; g++) {
                uint32_t kb0, kb1, kb2, kb3, kc0, kc1, kc2, kc3;
                const uint32_t boff =
                    (uint32_t)swz(g * 16 + browp, ks * 16 + bcolp) * 2;
                ldsm_x4(kb0, kb1, kb2, kb3, uKh + boff);
                ldsm_x4(kc0, kc1, kc2, kc3, uKl + boff);
                const int j0 = g * 2, j1 = g * 2 + 1;
                mma_bf16(s_[j0][0], s_[j0][1], s_[j0][2], s_[j0][3], h0, h1, h2, h3, kb0, kb1);
                mma_bf16(s_[j0][0], s_[j0][1], s_[j0][2], s_[j0][3], h0, h1, h2, h3, kc0, kc1);
                mma_bf16(s_[j0][0], s_[j0][1], s_[j0][2], s_[j0][3], l0, l1, l2, l3, kb0, kb1);
                mma_bf16(s_[j1][0], s_[j1][1], s_[j1][2], s_[j1][3], h0, h1, h2, h3, kb2, kb3);
                mma_bf16(s_[j1][0], s_[j1][1], s_[j1][2], s_[j1][3], h0, h1, h2, h3, kc2, kc3);
                mma_bf16(s_[j1][0], s_[j1][1], s_[j1][2], s_[j1][3], l0, l1, l2, l3, kb2, kb3);
            }
        }

        // ---- online softmax (rows fully in-warp) ----
        float mx0 = -1e30f, mx1 = -1e30f;
        #pragma unroll
        for (int j = 0; j < 8; j++) {
            const float b0 = bias[j * 8 + ecol2];
            const float b1 = bias[j * 8 + ecol2 + 1];
            s_[j][0] = fmaf(s_[j][0], 0.125f, b0);
            s_[j][1] = fmaf(s_[j][1], 0.125f, b1);
            s_[j][2] = fmaf(s_[j][2], 0.125f, b0);
            s_[j][3] = fmaf(s_[j][3], 0.125f, b1);
            mx0 = fmaxf(mx0, fmaxf(s_[j][0], s_[j][1]));
            mx1 = fmaxf(mx1, fmaxf(s_[j][2], s_[j][3]));
        }
        #pragma unroll
        for (int d = 1; d < 4; d <<= 1) {
            mx0 = fmaxf(mx0, __shfl_xor_sync(0xffffffffu, mx0, d));
            mx1 = fmaxf(mx1, __shfl_xor_sync(0xffffffffu, mx1, d));
        }
        const float mn0 = fmaxf(mr0, mx0);
        const float mn1 = fmaxf(mr1, mx1);
        const float al0 = __expf(mr0 - mn0);
        const float al1 = __expf(mr1 - mn1);
        mr0 = mn0; mr1 = mn1;

        float rs0 = 0.f, rs1 = 0.f;
        #pragma unroll
        for (int j = 0; j < 8; j++) {
            s_[j][0] = __expf(s_[j][0] - mn0);
            s_[j][1] = __expf(s_[j][1] - mn0);
            s_[j][2] = __expf(s_[j][2] - mn1);
            s_[j][3] = __expf(s_[j][3] - mn1);
            rs0 += s_[j][0] + s_[j][1];
            rs1 += s_[j][2] + s_[j][3];
        }
        #pragma unroll
        for (int d = 1; d < 4; d <<= 1) {
            rs0 += __shfl_xor_sync(0xffffffffu, rs0, d);
            rs1 += __shfl_xor_sync(0xffffffffu, rs1, d);
        }
        lr0 = lr0 * al0 + rs0;
        lr1 = lr1 * al1 + rs1;
        #pragma unroll
        for (int j = 0; j < 8; j++) {
            o[j][0] *= al0; o[j][1] *= al0;
            o[j][2] *= al1; o[j][3] *= al1;
        }

        // ---- O += P * V (split-bf16; P acc-frags -> A-frags directly) ----
        #pragma unroll
        for (int kf = 0; kf < 4; kf++) {
            __nv_bfloat16 ph[8], pl[8];
            splitp(s_[2 * kf][0], ph[0], pl[0]);
            splitp(s_[2 * kf][1], ph[1], pl[1]);
            splitp(s_[2 * kf][2], ph[2], pl[2]);
            splitp(s_[2 * kf][3], ph[3], pl[3]);
            splitp(s_[2 * kf + 1][0], ph[4], pl[4]);
            splitp(s_[2 * kf + 1][1], ph[5], pl[5]);
            splitp(s_[2 * kf + 1][2], ph[6], pl[6]);
            splitp(s_[2 * kf + 1][3], ph[7], pl[7]);
            const uint32_t ah0 = packbf(ph[0], ph[1]), ah1 = packbf(ph[2], ph[3]);
            const uint32_t ah2 = packbf(ph[4], ph[5]), ah3 = packbf(ph[6], ph[7]);
            const uint32_t am0 = packbf(pl[0], pl[1]), am1 = packbf(pl[2], pl[3]);
            const uint32_t am2 = packbf(pl[4], pl[5]), am3 = packbf(pl[6], pl[7]);
            #pragma unroll
            for (int g = 0; g < 4; g++) {
                uint32_t v0, v1, v2, v3, u0, u1, u2, u3;
                const uint32_t voff =
                    (uint32_t)swz(kf * 16 + vrowp, g * 16 + vcolp) * 2;
                ldsm_x4_t(v0, v1, v2, v3, uVh + voff);
                ldsm_x4_t(u0, u1, u2, u3, uVl + voff);
                const int d0 = g * 2, d1 = g * 2 + 1;
                mma_bf16(o[d0][0], o[d0][1], o[d0][2], o[d0][3], ah0, ah1, ah2, ah3, v0, v1);
                mma_bf16(o[d0][0], o[d0][1], o[d0][2], o[d0][3], ah0, ah1, ah2, ah3, u0, u1);
                mma_bf16(o[d0][0], o[d0][1], o[d0][2], o[d0][3], am0, am1, am2, am3, v0, v1);
                mma_bf16(o[d1][0], o[d1][1], o[d1][2], o[d1][3], ah0, ah1, ah2, ah3, v2, v3);
                mma_bf16(o[d1][0], o[d1][1], o[d1][2], o[d1][3], ah0, ah1, ah2, ah3, u2, u3);
                mma_bf16(o[d1][0], o[d1][1], o[d1][2], o[d1][3], am0, am1, am2, am3, v2, v3);
            }
        }
    }

    // ---- epilogue: normalize, write merged [b*SEQ+s][HID] fp32 ----
    const float inv0 = 1.f / lr0;
    const float inv1 = 1.f / lr1;
    const int erow = lane >> 2;
    const size_t r0g = (size_t)(b * SEQ + q0 + m0 + erow) * HID + h * HD;
    const size_t r1g = r0g + 8 * HID;
    #pragma unroll
    for (int dt = 0; dt < 8; dt++) {
        const int cc = dt * 8 + ecol2;
        *(float2*)(g_mrg + r0g + cc) = make_float2(o[dt][0] * inv0, o[dt][1] * inv0);
        *(float2*)(g_mrg + r1g + cc) = make_float2(o[dt][2] * inv1, o[dt][3] * inv1);
    }
}

// ---------------------------------------------------------------------------
extern "C" void kernel_launch(void* const* d_in, const int* in_sizes, int n_in,
                              void* d_out, int out_size)
{
    const float*         x    = (const float*)d_in[0];
    const unsigned char* mask = (const unsigned char*)d_in[1];
    const float*         Wq   = (const float*)d_in[2];
    const float*         Wk   = (const float*)d_in[3];
    const float*         Wv   = (const float*)d_in[4];
    const float*         Wp   = (const float*)d_in[5];
    float*               out  = (float*)d_out;

    cudaFuncSetAttribute(attn_mma, cudaFuncAttributeMaxDynamicSharedMemorySize,
                         ATTN_SMEM);
    cudaFuncSetAttribute(tc_gemm, cudaFuncAttributeMaxDynamicSharedMemorySize,
                         GEMM_SMEM);

    dim3 blk(256);
    decode_mask<<<1, 256>>>(mask, in_sizes[1]);
    // QKV projections (Q -> fp32, K/V -> pre-split bf16 hi/lo)
    tc_gemm<<<dim3(HID / 64, MROWS / 128, 3), blk, GEMM_SMEM>>>(x, 0, Wq, Wk, Wv, nullptr, 0);
    // Attention on tensor cores, cp.async double-buffered K/V
    attn_mma<<<dim3(SEQ / 128, BATCH * NH), blk, ATTN_SMEM>>>();
    // Output projection
    tc_gemm<<<dim3(HID / 64, MROWS / 128, 1), blk, GEMM_SMEM>>>(nullptr, 1, Wp, Wp, Wp, out, 1);
}